// round 1
// baseline (speedup 1.0000x reference)
#include <cuda_runtime.h>
#include <cuda_bf16.h>
#include <stdint.h>

// Problem constants (fixed shapes from reference)
#define BB 8
#define SS 4096
#define EE 1024
#define GG 2048
#define VV 256
#define PP 512

// Scratch: pooled patch embeddings (bf16 values stored as f32), 4096 x 1024
__device__ float g_pooled[(size_t)BB * PP * EE];

// ---------------------------------------------------------------------------
// bf16 emulation helpers (matches XLA: compute in f32, round-to-nearest-even)
// ---------------------------------------------------------------------------
__device__ __forceinline__ float bf_round(float x) {
    return __bfloat162float(__float2bfloat16(x));
}
__device__ __forceinline__ float bf_add(float a_bf, float x_bf) {
    return bf_round(a_bf + x_bf);
}

// ---------------------------------------------------------------------------
// Kernel 1: byte_embeds = bf16(embed_table[bytes]) written as f32
// One float4 per thread, grid-stride not needed (exact sizing).
// ---------------------------------------------------------------------------
__global__ void gather_kernel(const int* __restrict__ bytes,
                              const float* __restrict__ table,
                              float* __restrict__ out) {
    int idx = blockIdx.x * blockDim.x + threadIdx.x;       // float4 index
    const int E4 = EE / 4;
    // total float4s = BB*SS*E4 = 8,388,608
    int token = idx / E4;
    int e4 = idx - token * E4;
    int byte = __ldg(&bytes[token]);
    float4 v = reinterpret_cast<const float4*>(table)[byte * E4 + e4];
    v.x = bf_round(v.x);
    v.y = bf_round(v.y);
    v.z = bf_round(v.z);
    v.w = bf_round(v.w);
    reinterpret_cast<float4*>(out)[idx] = v;
}

// ---------------------------------------------------------------------------
// Kernel 2: patch pooling with exact bf16 sequential-accumulation semantics.
// One block per (batch, patch). patch_ids sorted -> contiguous range via
// binary search. 256 threads, 4 consecutive dims each (float4 gathers).
// ---------------------------------------------------------------------------
__device__ __forceinline__ int lower_bound_dev(const int* __restrict__ a, int n, int v) {
    int lo = 0, hi = n;
    while (lo < hi) {
        int mid = (lo + hi) >> 1;
        if (a[mid] < v) lo = mid + 1; else hi = mid;
    }
    return lo;
}

__global__ __launch_bounds__(256) void pool_kernel(const int* __restrict__ bytes,
                                                   const int* __restrict__ patch_ids,
                                                   const float* __restrict__ table) {
    int p = blockIdx.x;            // patch 0..511
    int b = blockIdx.y;            // batch 0..7
    const int* pid = patch_ids + b * SS;

    // every thread does the search redundantly (cheap, data in L1/L2)
    int lo = lower_bound_dev(pid, SS, p);
    int hi = lower_bound_dev(pid, SS, p + 1);
    int cnt = hi - lo;

    int tid = threadIdx.x;         // owns dims [tid*4, tid*4+4)
    float acc0 = 0.f, acc1 = 0.f, acc2 = 0.f, acc3 = 0.f;   // bf16 values in f32

    const int E4 = EE / 4;
    for (int t = lo; t < hi; t++) {
        int byte = __ldg(&bytes[b * SS + t]);
        float4 v = reinterpret_cast<const float4*>(table)[byte * E4 + tid];
        // segment_sum in bf16: round each operand to bf16, add, round result
        acc0 = bf_add(acc0, bf_round(v.x));
        acc1 = bf_add(acc1, bf_round(v.y));
        acc2 = bf_add(acc2, bf_round(v.z));
        acc3 = bf_add(acc3, bf_round(v.w));
    }

    float4 outv;
    if (cnt > 0) {
        float inv = (float)cnt;    // count in bf16 is exact for cnt <= 256
        outv.x = bf_round(acc0 / inv);
        outv.y = bf_round(acc1 / inv);
        outv.z = bf_round(acc2 / inv);
        outv.w = bf_round(acc3 / inv);
    } else {
        outv.x = outv.y = outv.z = outv.w = 0.f;
    }
    size_t row = (size_t)(b * PP + p);
    reinterpret_cast<float4*>(g_pooled)[row * E4 + tid] = outv;
}

// ---------------------------------------------------------------------------
// Kernel 3: patch_mask[b, p] = (p <= patch_ids[b, S-1])
// ---------------------------------------------------------------------------
__global__ void mask_kernel(const int* __restrict__ patch_ids,
                            float* __restrict__ mask) {
    int i = blockIdx.x * blockDim.x + threadIdx.x;   // 0..4095
    int b = i / PP;
    int p = i - b * PP;
    int mx = __ldg(&patch_ids[b * SS + SS - 1]);
    mask[i] = (p <= mx) ? 1.0f : 0.0f;
}

// ---------------------------------------------------------------------------
// Kernel 4: SGEMM  C[M,N] = A[M,K] * W[K,N] + bias[N]
// M = 4096 (B*P), K = 1024 (E), N = 2048 (G). f32 SIMT, 128x128x8 tiles,
// 8x8 per-thread micro-tile, 256 threads.
// ---------------------------------------------------------------------------
#define BM 128
#define BN 128
#define BK 8
#define TM 8
#define TN 8

__global__ __launch_bounds__(256) void sgemm_kernel(const float* __restrict__ W,
                                                    const float* __restrict__ bias,
                                                    float* __restrict__ C) {
    const float* A = g_pooled;
    const int M = BB * PP;   // 4096
    const int N = GG;        // 2048
    const int K = EE;        // 1024
    (void)M;

    __shared__ float As[BK][BM];
    __shared__ float Bs[BK][BN];

    int bm = blockIdx.y * BM;
    int bn = blockIdx.x * BN;
    int tid = threadIdx.x;
    int tx = tid & 15;        // 0..15 -> n tile
    int ty = tid >> 4;        // 0..15 -> m tile

    // A load mapping: row = tid>>1 (0..127), kg = (tid&1)*4
    int a_row = tid >> 1;
    int a_kg  = (tid & 1) * 4;
    // B load mapping: k = tid>>5 (0..7), n = (tid&31)*4
    int b_k = tid >> 5;
    int b_n = (tid & 31) * 4;

    float acc[TM][TN];
    #pragma unroll
    for (int i = 0; i < TM; i++)
        #pragma unroll
        for (int j = 0; j < TN; j++) acc[i][j] = 0.f;

    for (int k0 = 0; k0 < K; k0 += BK) {
        // load A tile (transposed into As[k][m])
        float4 av = reinterpret_cast<const float4*>(A + (size_t)(bm + a_row) * K + k0 + a_kg)[0];
        As[a_kg + 0][a_row] = av.x;
        As[a_kg + 1][a_row] = av.y;
        As[a_kg + 2][a_row] = av.z;
        As[a_kg + 3][a_row] = av.w;
        // load B tile
        float4 bv = reinterpret_cast<const float4*>(W + (size_t)(k0 + b_k) * N + bn + b_n)[0];
        *reinterpret_cast<float4*>(&Bs[b_k][b_n]) = bv;
        __syncthreads();

        #pragma unroll
        for (int k = 0; k < BK; k++) {
            float a[TM], bb[TN];
            #pragma unroll
            for (int i = 0; i < TM; i += 4) {
                float4 t = *reinterpret_cast<float4*>(&As[k][ty * TM + i]);
                a[i] = t.x; a[i+1] = t.y; a[i+2] = t.z; a[i+3] = t.w;
            }
            #pragma unroll
            for (int j = 0; j < TN; j += 4) {
                float4 t = *reinterpret_cast<float4*>(&Bs[k][tx * TN + j]);
                bb[j] = t.x; bb[j+1] = t.y; bb[j+2] = t.z; bb[j+3] = t.w;
            }
            #pragma unroll
            for (int i = 0; i < TM; i++)
                #pragma unroll
                for (int j = 0; j < TN; j++)
                    acc[i][j] += a[i] * bb[j];
        }
        __syncthreads();
    }

    // epilogue: add bias, write
    #pragma unroll
    for (int i = 0; i < TM; i++) {
        int m = bm + ty * TM + i;
        #pragma unroll
        for (int j = 0; j < TN; j += 4) {
            int n = bn + tx * TN + j;
            float4 o;
            o.x = acc[i][j + 0] + bias[n + 0];
            o.y = acc[i][j + 1] + bias[n + 1];
            o.z = acc[i][j + 2] + bias[n + 2];
            o.w = acc[i][j + 3] + bias[n + 3];
            *reinterpret_cast<float4*>(&C[(size_t)m * N + n]) = o;
        }
    }
}

// ---------------------------------------------------------------------------
// Launch
// ---------------------------------------------------------------------------
extern "C" void kernel_launch(void* const* d_in, const int* in_sizes, int n_in,
                              void* d_out, int out_size) {
    const int*   bytes    = (const int*)d_in[0];
    const int*   pids     = (const int*)d_in[1];
    const float* table    = (const float*)d_in[2];
    const float* W        = (const float*)d_in[3];
    const float* bias     = (const float*)d_in[4];

    float* out         = (float*)d_out;
    float* byte_embeds = out;                                    // 8*4096*1024
    float* patch_embs  = out + (size_t)BB * SS * EE;             // 8*512*2048
    float* mask        = patch_embs + (size_t)BB * PP * GG;      // 8*512

    // 1) gather: 8.4M float4s
    {
        int n4 = BB * SS * (EE / 4);
        gather_kernel<<<n4 / 256, 256>>>(bytes, table, byte_embeds);
    }
    // 2) pooling: one block per (patch, batch)
    pool_kernel<<<dim3(PP, BB), 256>>>(bytes, pids, table);
    // 3) mask
    mask_kernel<<<(BB * PP) / 256, 256>>>(pids, mask);
    // 4) GEMM: (4096 x 1024) @ (1024 x 2048) + bias
    sgemm_kernel<<<dim3(GG / BN, (BB * PP) / BM), 256>>>(W, bias, patch_embs);
}

// round 4
// speedup vs baseline: 2.4885x; 2.4885x over previous
#include <cuda_runtime.h>
#include <cuda_bf16.h>
#include <stdint.h>

// Problem constants (fixed shapes from reference)
#define BB 8
#define SS 4096
#define EE 1024
#define GG 2048
#define VV 256
#define PP 512

#define MM (BB * PP)   // 4096 GEMM M
#define NN GG          // 2048 GEMM N
#define KK EE          // 1024 GEMM K

// Scratch (device globals — no allocation allowed)
__device__ __nv_bfloat16 g_A[(size_t)MM * KK];      // pooled patch embeddings, bf16, [M,K]
__device__ __nv_bfloat16 g_Wt_hi[(size_t)NN * KK];  // hi part of W^T [N,K]
__device__ __nv_bfloat16 g_Wt_lo[(size_t)NN * KK];  // lo part (residual) of W^T [N,K]

// ---------------------------------------------------------------------------
// bf16 emulation helpers
// ---------------------------------------------------------------------------
__device__ __forceinline__ float bf_round(float x) {
    return __bfloat162float(__float2bfloat16(x));
}
__device__ __forceinline__ float bf_add(float a_bf, float x_bf) {
    return bf_round(a_bf + x_bf);
}

// ---------------------------------------------------------------------------
// Kernel 1: byte_embeds = bf16(embed_table[bytes]) written as f32
// ---------------------------------------------------------------------------
__global__ void gather_kernel(const int* __restrict__ bytes,
                              const float* __restrict__ table,
                              float* __restrict__ out) {
    int idx = blockIdx.x * blockDim.x + threadIdx.x;       // float4 index
    const int E4 = EE / 4;
    int token = idx / E4;
    int e4 = idx - token * E4;
    int byte = __ldg(&bytes[token]);
    float4 v = reinterpret_cast<const float4*>(table)[byte * E4 + e4];
    v.x = bf_round(v.x);
    v.y = bf_round(v.y);
    v.z = bf_round(v.z);
    v.w = bf_round(v.w);
    reinterpret_cast<float4*>(out)[idx] = v;
}

// ---------------------------------------------------------------------------
// Kernel 2: patch pooling with exact bf16 sequential-accumulation semantics.
// ---------------------------------------------------------------------------
__device__ __forceinline__ int lower_bound_dev(const int* __restrict__ a, int n, int v) {
    int lo = 0, hi = n;
    while (lo < hi) {
        int mid = (lo + hi) >> 1;
        if (a[mid] < v) lo = mid + 1; else hi = mid;
    }
    return lo;
}

__global__ __launch_bounds__(256) void pool_kernel(const int* __restrict__ bytes,
                                                   const int* __restrict__ patch_ids,
                                                   const float* __restrict__ table) {
    int p = blockIdx.x;            // patch 0..511
    int b = blockIdx.y;            // batch 0..7
    const int* pid = patch_ids + b * SS;

    int lo = lower_bound_dev(pid, SS, p);
    int hi = lower_bound_dev(pid, SS, p + 1);
    int cnt = hi - lo;

    int tid = threadIdx.x;         // owns dims [tid*4, tid*4+4)
    float acc0 = 0.f, acc1 = 0.f, acc2 = 0.f, acc3 = 0.f;

    const int E4 = EE / 4;
    for (int t = lo; t < hi; t++) {
        int byte = __ldg(&bytes[b * SS + t]);
        float4 v = reinterpret_cast<const float4*>(table)[byte * E4 + tid];
        acc0 = bf_add(acc0, bf_round(v.x));
        acc1 = bf_add(acc1, bf_round(v.y));
        acc2 = bf_add(acc2, bf_round(v.z));
        acc3 = bf_add(acc3, bf_round(v.w));
    }

    float o0, o1, o2, o3;
    if (cnt > 0) {
        float inv = (float)cnt;
        o0 = bf_round(acc0 / inv);
        o1 = bf_round(acc1 / inv);
        o2 = bf_round(acc2 / inv);
        o3 = bf_round(acc3 / inv);
    } else {
        o0 = o1 = o2 = o3 = 0.f;
    }
    __nv_bfloat162 p0 = __floats2bfloat162_rn(o0, o1);
    __nv_bfloat162 p1 = __floats2bfloat162_rn(o2, o3);
    uint2 pack;
    pack.x = *reinterpret_cast<uint32_t*>(&p0);
    pack.y = *reinterpret_cast<uint32_t*>(&p1);
    size_t row = (size_t)(b * PP + p);
    reinterpret_cast<uint2*>(g_A)[row * (EE / 4) + tid] = pack;
}

// ---------------------------------------------------------------------------
// Kernel 3: patch_mask[b, p] = (p <= patch_ids[b, S-1])
// ---------------------------------------------------------------------------
__global__ void mask_kernel(const int* __restrict__ patch_ids,
                            float* __restrict__ mask) {
    int i = blockIdx.x * blockDim.x + threadIdx.x;   // 0..4095
    int b = i / PP;
    int p = i - b * PP;
    int mx = __ldg(&patch_ids[b * SS + SS - 1]);
    mask[i] = (p <= mx) ? 1.0f : 0.0f;
}

// ---------------------------------------------------------------------------
// Kernel 4: W prep — transpose [K,N] f32 -> [N,K] split-bf16 (hi + residual lo)
// ---------------------------------------------------------------------------
__global__ __launch_bounds__(256) void wprep_kernel(const float* __restrict__ W) {
    __shared__ float t[32][33];
    int n0 = blockIdx.x * 32, k0 = blockIdx.y * 32;
    int tx = threadIdx.x, ty = threadIdx.y;   // block (32, 8)
    #pragma unroll
    for (int i = 0; i < 32; i += 8)
        t[ty + i][tx] = W[(size_t)(k0 + ty + i) * NN + n0 + tx];
    __syncthreads();
    #pragma unroll
    for (int i = 0; i < 32; i += 8) {
        float w = t[tx][ty + i];
        __nv_bfloat16 hi = __float2bfloat16(w);
        __nv_bfloat16 lo = __float2bfloat16(w - __bfloat162float(hi));
        size_t off = (size_t)(n0 + ty + i) * KK + k0 + tx;
        g_Wt_hi[off] = hi;
        g_Wt_lo[off] = lo;
    }
}

// ---------------------------------------------------------------------------
// Kernel 5: split-bf16 tensor-core GEMM via mma.sync.m16n8k16
// C[M,N] = A[M,K] @ (Wt_hi + Wt_lo)[N,K]^T + bias, f32 accumulation
// CTA 128x128x32, 8 warps (4m x 2n), warp tile 32x64, 2-stage cp.async.
// ---------------------------------------------------------------------------
#define BM 128
#define BN 128
#define BK 32
#define ROWB 80                          // padded row stride in bytes (64B data + 16B pad)
#define STAGE_BYTES (BM * ROWB)          // 10240 per operand per stage
#define SM_A  0
#define SM_BH (2 * STAGE_BYTES)          // 20480
#define SM_BL (4 * STAGE_BYTES)          // 40960
#define GEMM_SMEM (6 * STAGE_BYTES)      // 61440

__device__ __forceinline__ uint32_t smem_u32(const void* p) {
    uint32_t a;
    asm("{ .reg .u64 t; cvta.to.shared.u64 t, %1; cvt.u32.u64 %0, t; }" : "=r"(a) : "l"(p));
    return a;
}
__device__ __forceinline__ void cp_async16(uint32_t saddr, const void* gaddr) {
    asm volatile("cp.async.cg.shared.global [%0], [%1], 16;\n" :: "r"(saddr), "l"(gaddr));
}
__device__ __forceinline__ void ldmatrix_x4(uint32_t* r, uint32_t addr) {
    asm volatile("ldmatrix.sync.aligned.m8n8.x4.shared.b16 {%0,%1,%2,%3}, [%4];"
                 : "=r"(r[0]), "=r"(r[1]), "=r"(r[2]), "=r"(r[3]) : "r"(addr));
}
__device__ __forceinline__ void mma_16816(float* c, const uint32_t* a, uint32_t b0, uint32_t b1) {
    asm volatile("mma.sync.aligned.m16n8k16.row.col.f32.bf16.bf16.f32 "
                 "{%0,%1,%2,%3}, {%4,%5,%6,%7}, {%8,%9}, {%0,%1,%2,%3};"
                 : "+f"(c[0]), "+f"(c[1]), "+f"(c[2]), "+f"(c[3])
                 : "r"(a[0]), "r"(a[1]), "r"(a[2]), "r"(a[3]), "r"(b0), "r"(b1));
}

__global__ __launch_bounds__(256, 1) void gemm_mma_kernel(const float* __restrict__ bias,
                                                          float* __restrict__ C) {
    extern __shared__ __align__(16) char smem[];
    uint32_t sbase = smem_u32(smem);

    const int tid = threadIdx.x;
    const int lane = tid & 31;
    const int wid = tid >> 5;
    const int wm = wid & 3;          // 0..3 -> m offset wm*32
    const int wn = wid >> 2;         // 0..1 -> n offset wn*64
    const int bm = blockIdx.y * BM;
    const int bn = blockIdx.x * BN;

    const __nv_bfloat16* Ag  = g_A     + (size_t)bm * KK;
    const __nv_bfloat16* Bhg = g_Wt_hi + (size_t)bn * KK;
    const __nv_bfloat16* Blg = g_Wt_lo + (size_t)bn * KK;

    // load: 512 16B-units per operand per stage, 2 per thread per operand
    auto load_stage = [&](int buf, int k0) {
        #pragma unroll
        for (int i = 0; i < 2; i++) {
            int unit = tid * 2 + i;
            int r = unit >> 2, j = unit & 3;
            uint32_t so = buf * STAGE_BYTES + r * ROWB + j * 16;
            size_t go = (size_t)r * KK + k0 + j * 8;
            cp_async16(sbase + SM_A  + so, Ag  + go);
            cp_async16(sbase + SM_BH + so, Bhg + go);
            cp_async16(sbase + SM_BL + so, Blg + go);
        }
        asm volatile("cp.async.commit_group;\n");
    };

    float acc[2][8][4];
    #pragma unroll
    for (int mt = 0; mt < 2; mt++)
        #pragma unroll
        for (int nt = 0; nt < 8; nt++)
            #pragma unroll
            for (int q = 0; q < 4; q++) acc[mt][nt][q] = 0.f;

    const int NC = KK / BK;   // 32
    load_stage(0, 0);

    const int lrow = lane & 15;
    const int lcol16 = (lane >> 4) * 16;

    for (int c = 0; c < NC; c++) {
        if (c + 1 < NC) {
            load_stage((c + 1) & 1, (c + 1) * BK);
            asm volatile("cp.async.wait_group 1;\n");
        } else {
            asm volatile("cp.async.wait_group 0;\n");
        }
        __syncthreads();

        uint32_t Ab  = sbase + SM_A  + (c & 1) * STAGE_BYTES;
        uint32_t Bhb = sbase + SM_BH + (c & 1) * STAGE_BYTES;
        uint32_t Blb = sbase + SM_BL + (c & 1) * STAGE_BYTES;

        #pragma unroll
        for (int ks = 0; ks < 2; ks++) {
            uint32_t af[2][4];
            #pragma unroll
            for (int mt = 0; mt < 2; mt++)
                ldmatrix_x4(af[mt], Ab + (wm * 32 + mt * 16 + lrow) * ROWB + ks * 32 + lcol16);
            #pragma unroll
            for (int ntp = 0; ntp < 4; ntp++) {
                uint32_t roff = (wn * 64 + ntp * 16 + lrow) * ROWB + ks * 32 + lcol16;
                uint32_t bfh[4], bfl[4];
                ldmatrix_x4(bfh, Bhb + roff);
                ldmatrix_x4(bfl, Blb + roff);
                #pragma unroll
                for (int mt = 0; mt < 2; mt++) {
                    mma_16816(acc[mt][2 * ntp + 0], af[mt], bfh[0], bfh[2]);
                    mma_16816(acc[mt][2 * ntp + 1], af[mt], bfh[1], bfh[3]);
                    mma_16816(acc[mt][2 * ntp + 0], af[mt], bfl[0], bfl[2]);
                    mma_16816(acc[mt][2 * ntp + 1], af[mt], bfl[1], bfl[3]);
                }
            }
        }
        __syncthreads();
    }

    // Epilogue: m16n8 fragment -> C. row = lane/4 (+8 for regs 2,3), col = 2*(lane%4)
    const int er = lane >> 2;
    const int ec = (lane & 3) * 2;
    #pragma unroll
    for (int mt = 0; mt < 2; mt++) {
        #pragma unroll
        for (int nt = 0; nt < 8; nt++) {
            int n = bn + wn * 64 + nt * 8 + ec;
            float b0 = bias[n], b1 = bias[n + 1];
            int m0 = bm + wm * 32 + mt * 16 + er;
            float2 o0 = make_float2(acc[mt][nt][0] + b0, acc[mt][nt][1] + b1);
            float2 o1 = make_float2(acc[mt][nt][2] + b0, acc[mt][nt][3] + b1);
            *reinterpret_cast<float2*>(C + (size_t)m0 * NN + n) = o0;
            *reinterpret_cast<float2*>(C + (size_t)(m0 + 8) * NN + n) = o1;
        }
    }
}

// ---------------------------------------------------------------------------
// Launch
// ---------------------------------------------------------------------------
extern "C" void kernel_launch(void* const* d_in, const int* in_sizes, int n_in,
                              void* d_out, int out_size) {
    const int*   bytes    = (const int*)d_in[0];
    const int*   pids     = (const int*)d_in[1];
    const float* table    = (const float*)d_in[2];
    const float* W        = (const float*)d_in[3];
    const float* bias     = (const float*)d_in[4];

    float* out         = (float*)d_out;
    float* byte_embeds = out;                                    // 8*4096*1024
    float* patch_embs  = out + (size_t)BB * SS * EE;             // 8*512*2048
    float* mask        = patch_embs + (size_t)BB * PP * GG;      // 8*512

    cudaFuncSetAttribute(gemm_mma_kernel,
                         cudaFuncAttributeMaxDynamicSharedMemorySize, GEMM_SMEM);

    // 1) W prep (independent of pooling)
    wprep_kernel<<<dim3(NN / 32, KK / 32), dim3(32, 8)>>>(W);
    // 2) gather: 8.4M float4s
    gather_kernel<<<BB * SS * (EE / 4) / 256, 256>>>(bytes, table, byte_embeds);
    // 3) pooling -> g_A (bf16)
    pool_kernel<<<dim3(PP, BB), 256>>>(bytes, pids, table);
    // 4) mask
    mask_kernel<<<(BB * PP) / 256, 256>>>(pids, mask);
    // 5) split-bf16 tensor-core GEMM: (4096 x 1024) @ (1024 x 2048) + bias
    gemm_mma_kernel<<<dim3(NN / BN, MM / BM), 256, GEMM_SMEM>>>(bias, patch_embs);
}

// round 5
// speedup vs baseline: 3.4586x; 1.3898x over previous
#include <cuda_runtime.h>
#include <cuda_bf16.h>
#include <cuda_fp16.h>
#include <stdint.h>

// Problem constants (fixed shapes from reference)
#define BB 8
#define SS 4096
#define EE 1024
#define GG 2048
#define VV 256
#define PP 512

#define MM (BB * PP)   // 4096 GEMM M
#define NN GG          // 2048 GEMM N
#define KK EE          // 1024 GEMM K

// Scratch (device globals — no allocation allowed)
__device__ __half g_A[(size_t)MM * KK];    // pooled patch embeddings, fp16 (exact bf16 values), [M,K]
__device__ __half g_Wt[(size_t)NN * KK];   // W transposed to [N,K], fp16

// ---------------------------------------------------------------------------
// bf16 emulation helpers
// ---------------------------------------------------------------------------
__device__ __forceinline__ float bf_round(float x) {
    return __bfloat162float(__float2bfloat16(x));
}
__device__ __forceinline__ float bf_add(float a_bf, float x_bf) {
    return bf_round(a_bf + x_bf);
}

// ---------------------------------------------------------------------------
// Kernel 1: byte_embeds = bf16(embed_table[bytes]) written as f32
// ---------------------------------------------------------------------------
__global__ void gather_kernel(const int* __restrict__ bytes,
                              const float* __restrict__ table,
                              float* __restrict__ out) {
    int idx = blockIdx.x * blockDim.x + threadIdx.x;       // float4 index
    const int E4 = EE / 4;
    int token = idx / E4;
    int e4 = idx - token * E4;
    int byte = __ldg(&bytes[token]);
    float4 v = reinterpret_cast<const float4*>(table)[byte * E4 + e4];
    v.x = bf_round(v.x);
    v.y = bf_round(v.y);
    v.z = bf_round(v.z);
    v.w = bf_round(v.w);
    reinterpret_cast<float4*>(out)[idx] = v;
}

// ---------------------------------------------------------------------------
// Kernel 2: patch pooling, exact bf16 sequential-accumulation semantics.
// Writes fp16 into g_A (bf16 values -> fp16 is lossless for normals).
// Also emits patch_mask (fused).
// ---------------------------------------------------------------------------
__device__ __forceinline__ int lower_bound_dev(const int* __restrict__ a, int n, int v) {
    int lo = 0, hi = n;
    while (lo < hi) {
        int mid = (lo + hi) >> 1;
        if (a[mid] < v) lo = mid + 1; else hi = mid;
    }
    return lo;
}

__global__ __launch_bounds__(256) void pool_kernel(const int* __restrict__ bytes,
                                                   const int* __restrict__ patch_ids,
                                                   const float* __restrict__ table,
                                                   float* __restrict__ mask) {
    int p = blockIdx.x;            // patch 0..511
    int b = blockIdx.y;            // batch 0..7
    const int* pid = patch_ids + b * SS;

    if (threadIdx.x == 0) {
        int mx = __ldg(&pid[SS - 1]);
        mask[b * PP + p] = (p <= mx) ? 1.0f : 0.0f;
    }

    int lo = lower_bound_dev(pid, SS, p);
    int hi = lower_bound_dev(pid, SS, p + 1);
    int cnt = hi - lo;

    int tid = threadIdx.x;         // owns dims [tid*4, tid*4+4)
    float acc0 = 0.f, acc1 = 0.f, acc2 = 0.f, acc3 = 0.f;

    const int E4 = EE / 4;
    for (int t = lo; t < hi; t++) {
        int byte = __ldg(&bytes[b * SS + t]);
        float4 v = reinterpret_cast<const float4*>(table)[byte * E4 + tid];
        acc0 = bf_add(acc0, bf_round(v.x));
        acc1 = bf_add(acc1, bf_round(v.y));
        acc2 = bf_add(acc2, bf_round(v.z));
        acc3 = bf_add(acc3, bf_round(v.w));
    }

    float o0, o1, o2, o3;
    if (cnt > 0) {
        float inv = (float)cnt;
        o0 = bf_round(acc0 / inv);
        o1 = bf_round(acc1 / inv);
        o2 = bf_round(acc2 / inv);
        o3 = bf_round(acc3 / inv);
    } else {
        o0 = o1 = o2 = o3 = 0.f;
    }
    __half2 h0 = __floats2half2_rn(o0, o1);
    __half2 h1 = __floats2half2_rn(o2, o3);
    uint2 pack;
    pack.x = *reinterpret_cast<uint32_t*>(&h0);
    pack.y = *reinterpret_cast<uint32_t*>(&h1);
    size_t row = (size_t)(b * PP + p);
    reinterpret_cast<uint2*>(g_A)[row * (EE / 4) + tid] = pack;
}

// ---------------------------------------------------------------------------
// Kernel 3: W prep — transpose [K,N] f32 -> [N,K] fp16 (tiled via SMEM)
// ---------------------------------------------------------------------------
__global__ __launch_bounds__(256) void wprep_kernel(const float* __restrict__ W) {
    __shared__ float t[32][33];
    int n0 = blockIdx.x * 32, k0 = blockIdx.y * 32;
    int tx = threadIdx.x, ty = threadIdx.y;   // block (32, 8)
    #pragma unroll
    for (int i = 0; i < 32; i += 8)
        t[ty + i][tx] = W[(size_t)(k0 + ty + i) * NN + n0 + tx];
    __syncthreads();
    #pragma unroll
    for (int i = 0; i < 32; i += 8)
        g_Wt[(size_t)(n0 + ty + i) * KK + k0 + tx] = __float2half_rn(t[tx][ty + i]);
}

// ---------------------------------------------------------------------------
// Kernel 4: fp16 tensor-core GEMM via mma.sync.m16n8k16.f32.f16.f16.f32
// C[M,N] = A[M,K] @ Wt[N,K]^T + bias, f32 accumulation
// CTA 128x128x32, 8 warps (4m x 2n), warp tile 32x64, 3-stage cp.async.
// ---------------------------------------------------------------------------
#define BM 128
#define BN 128
#define BK 32
#define STAGES 3
#define ROWB 80                          // padded row stride in bytes (64B data + 16B pad)
#define OP_BYTES (BM * ROWB)             // 10240 per operand per stage
#define STAGE_BYTES (2 * OP_BYTES)       // A + B = 20480
#define GEMM_SMEM (STAGES * STAGE_BYTES) // 61440

__device__ __forceinline__ uint32_t smem_u32(const void* p) {
    uint32_t a;
    asm("{ .reg .u64 t; cvta.to.shared.u64 t, %1; cvt.u32.u64 %0, t; }" : "=r"(a) : "l"(p));
    return a;
}
__device__ __forceinline__ void cp_async16(uint32_t saddr, const void* gaddr) {
    asm volatile("cp.async.cg.shared.global [%0], [%1], 16;\n" :: "r"(saddr), "l"(gaddr));
}
__device__ __forceinline__ void ldmatrix_x4(uint32_t* r, uint32_t addr) {
    asm volatile("ldmatrix.sync.aligned.m8n8.x4.shared.b16 {%0,%1,%2,%3}, [%4];"
                 : "=r"(r[0]), "=r"(r[1]), "=r"(r[2]), "=r"(r[3]) : "r"(addr));
}
__device__ __forceinline__ void mma_16816(float* c, const uint32_t* a, uint32_t b0, uint32_t b1) {
    asm volatile("mma.sync.aligned.m16n8k16.row.col.f32.f16.f16.f32 "
                 "{%0,%1,%2,%3}, {%4,%5,%6,%7}, {%8,%9}, {%0,%1,%2,%3};"
                 : "+f"(c[0]), "+f"(c[1]), "+f"(c[2]), "+f"(c[3])
                 : "r"(a[0]), "r"(a[1]), "r"(a[2]), "r"(a[3]), "r"(b0), "r"(b1));
}

__global__ __launch_bounds__(256, 1) void gemm_mma_kernel(const float* __restrict__ bias,
                                                          float* __restrict__ C) {
    extern __shared__ __align__(16) char smem[];
    uint32_t sbase = smem_u32(smem);

    const int tid = threadIdx.x;
    const int lane = tid & 31;
    const int wid = tid >> 5;
    const int wm = wid & 3;          // 0..3 -> m offset wm*32
    const int wn = wid >> 2;         // 0..1 -> n offset wn*64
    const int bm = blockIdx.y * BM;
    const int bn = blockIdx.x * BN;

    const __half* Ag = g_A  + (size_t)bm * KK;
    const __half* Bg = g_Wt + (size_t)bn * KK;

    // load: 512 16B-units per operand per stage, 2 per thread per operand
    auto load_stage = [&](int buf, int k0) {
        #pragma unroll
        for (int i = 0; i < 2; i++) {
            int unit = tid * 2 + i;
            int r = unit >> 2, j = unit & 3;
            uint32_t so = buf * STAGE_BYTES + r * ROWB + j * 16;
            size_t go = (size_t)r * KK + k0 + j * 8;
            cp_async16(sbase + so, Ag + go);
            cp_async16(sbase + so + OP_BYTES, Bg + go);
        }
        asm volatile("cp.async.commit_group;\n");
    };

    float acc[2][8][4];
    #pragma unroll
    for (int mt = 0; mt < 2; mt++)
        #pragma unroll
        for (int nt = 0; nt < 8; nt++)
            #pragma unroll
            for (int q = 0; q < 4; q++) acc[mt][nt][q] = 0.f;

    const int NC = KK / BK;   // 32
    load_stage(0, 0);
    load_stage(1, BK);

    const int lrow = lane & 15;
    const int lcol16 = (lane >> 4) * 16;

    for (int c = 0; c < NC; c++) {
        if (c < NC - 1) {
            asm volatile("cp.async.wait_group 1;\n");
        } else {
            asm volatile("cp.async.wait_group 0;\n");
        }
        __syncthreads();   // stage c visible to all; all readers of stage c-1 done

        if (c + 2 < NC)
            load_stage((c + 2) % STAGES, (c + 2) * BK);

        uint32_t Ab = sbase + (c % STAGES) * STAGE_BYTES;
        uint32_t Bb = Ab + OP_BYTES;

        #pragma unroll
        for (int ks = 0; ks < 2; ks++) {
            uint32_t af[2][4];
            #pragma unroll
            for (int mt = 0; mt < 2; mt++)
                ldmatrix_x4(af[mt], Ab + (wm * 32 + mt * 16 + lrow) * ROWB + ks * 32 + lcol16);
            #pragma unroll
            for (int ntp = 0; ntp < 4; ntp++) {
                uint32_t bf[4];
                ldmatrix_x4(bf, Bb + (wn * 64 + ntp * 16 + lrow) * ROWB + ks * 32 + lcol16);
                #pragma unroll
                for (int mt = 0; mt < 2; mt++) {
                    mma_16816(acc[mt][2 * ntp + 0], af[mt], bf[0], bf[2]);
                    mma_16816(acc[mt][2 * ntp + 1], af[mt], bf[1], bf[3]);
                }
            }
        }
    }

    // Epilogue: m16n8 fragment -> C. row = lane/4 (+8 for regs 2,3), col = 2*(lane%4)
    const int er = lane >> 2;
    const int ec = (lane & 3) * 2;
    #pragma unroll
    for (int mt = 0; mt < 2; mt++) {
        #pragma unroll
        for (int nt = 0; nt < 8; nt++) {
            int n = bn + wn * 64 + nt * 8 + ec;
            float b0 = bias[n], b1 = bias[n + 1];
            int m0 = bm + wm * 32 + mt * 16 + er;
            float2 o0 = make_float2(acc[mt][nt][0] + b0, acc[mt][nt][1] + b1);
            float2 o1 = make_float2(acc[mt][nt][2] + b0, acc[mt][nt][3] + b1);
            *reinterpret_cast<float2*>(C + (size_t)m0 * NN + n) = o0;
            *reinterpret_cast<float2*>(C + (size_t)(m0 + 8) * NN + n) = o1;
        }
    }
}

// ---------------------------------------------------------------------------
// Launch — gather forked onto a side stream (captured fork/join) so its
// DRAM-bound writes overlap the L2/tensor-bound pool+GEMM chain.
// ---------------------------------------------------------------------------
extern "C" void kernel_launch(void* const* d_in, const int* in_sizes, int n_in,
                              void* d_out, int out_size) {
    const int*   bytes    = (const int*)d_in[0];
    const int*   pids     = (const int*)d_in[1];
    const float* table    = (const float*)d_in[2];
    const float* W        = (const float*)d_in[3];
    const float* bias     = (const float*)d_in[4];

    float* out         = (float*)d_out;
    float* byte_embeds = out;                                    // 8*4096*1024
    float* patch_embs  = out + (size_t)BB * SS * EE;             // 8*512*2048
    float* mask        = patch_embs + (size_t)BB * PP * GG;      // 8*512

    static cudaStream_t s_side = nullptr;
    static cudaEvent_t e_fork = nullptr, e_join = nullptr;
    if (s_side == nullptr) {
        cudaStreamCreateWithFlags(&s_side, cudaStreamNonBlocking);
        cudaEventCreateWithFlags(&e_fork, cudaEventDisableTiming);
        cudaEventCreateWithFlags(&e_join, cudaEventDisableTiming);
        cudaFuncSetAttribute(gemm_mma_kernel,
                             cudaFuncAttributeMaxDynamicSharedMemorySize, GEMM_SMEM);
    }

    // Fork: gather on side stream
    cudaEventRecord(e_fork, 0);
    cudaStreamWaitEvent(s_side, e_fork, 0);
    gather_kernel<<<BB * SS * (EE / 4) / 256, 256, 0, s_side>>>(bytes, table, byte_embeds);
    cudaEventRecord(e_join, s_side);

    // Main chain: wprep -> pool(+mask) -> GEMM
    wprep_kernel<<<dim3(NN / 32, KK / 32), dim3(32, 8)>>>(W);
    pool_kernel<<<dim3(PP, BB), 256>>>(bytes, pids, table, mask);
    gemm_mma_kernel<<<dim3(NN / BN, MM / BM), 256, GEMM_SMEM>>>(bias, patch_embs);

    // Join: launch stream completes only after gather is done
    cudaStreamWaitEvent(0, e_join, 0);
}

// round 6
// speedup vs baseline: 3.8405x; 1.1104x over previous
#include <cuda_runtime.h>
#include <cuda_bf16.h>
#include <cuda_fp16.h>
#include <stdint.h>

// Problem constants (fixed shapes from reference)
#define BB 8
#define SS 4096
#define EE 1024
#define GG 2048
#define VV 256
#define PP 512

#define MM (BB * PP)   // 4096 GEMM M
#define NN GG          // 2048 GEMM N
#define KK EE          // 1024 GEMM K

// Scratch (device globals — no allocation allowed)
__device__ __half g_A[(size_t)MM * KK];    // pooled patch embeddings, fp16 (exact bf16 values), [M,K]
__device__ __half g_Wt[(size_t)NN * KK];   // W transposed to [N,K], fp16

// ---------------------------------------------------------------------------
// bf16 emulation helpers
// ---------------------------------------------------------------------------
__device__ __forceinline__ float bf_round(float x) {
    return __bfloat162float(__float2bfloat16(x));
}
__device__ __forceinline__ float bf_add(float a_bf, float x_bf) {
    return bf_round(a_bf + x_bf);
}

// ---------------------------------------------------------------------------
// Kernel 1: byte_embeds = bf16(embed_table[bytes]) written as f32
// ---------------------------------------------------------------------------
__global__ void gather_kernel(const int* __restrict__ bytes,
                              const float* __restrict__ table,
                              float* __restrict__ out) {
    int idx = blockIdx.x * blockDim.x + threadIdx.x;       // float4 index
    const int E4 = EE / 4;
    int token = idx / E4;
    int e4 = idx - token * E4;
    int byte = __ldg(&bytes[token]);
    float4 v = reinterpret_cast<const float4*>(table)[byte * E4 + e4];
    v.x = bf_round(v.x);
    v.y = bf_round(v.y);
    v.z = bf_round(v.z);
    v.w = bf_round(v.w);
    reinterpret_cast<float4*>(out)[idx] = v;
}

// ---------------------------------------------------------------------------
// Kernel 2: patch pooling, exact bf16 sequential-accumulation semantics.
// Writes fp16 into g_A; fused patch_mask store.
// ---------------------------------------------------------------------------
__device__ __forceinline__ int lower_bound_dev(const int* __restrict__ a, int n, int v) {
    int lo = 0, hi = n;
    while (lo < hi) {
        int mid = (lo + hi) >> 1;
        if (a[mid] < v) lo = mid + 1; else hi = mid;
    }
    return lo;
}

__global__ __launch_bounds__(256) void pool_kernel(const int* __restrict__ bytes,
                                                   const int* __restrict__ patch_ids,
                                                   const float* __restrict__ table,
                                                   float* __restrict__ mask) {
    int p = blockIdx.x;            // patch 0..511
    int b = blockIdx.y;            // batch 0..7
    const int* pid = patch_ids + b * SS;

    if (threadIdx.x == 0) {
        int mx = __ldg(&pid[SS - 1]);
        mask[b * PP + p] = (p <= mx) ? 1.0f : 0.0f;
    }

    int lo = lower_bound_dev(pid, SS, p);
    int hi = lower_bound_dev(pid, SS, p + 1);
    int cnt = hi - lo;

    int tid = threadIdx.x;         // owns dims [tid*4, tid*4+4)
    float acc0 = 0.f, acc1 = 0.f, acc2 = 0.f, acc3 = 0.f;

    const int E4 = EE / 4;
    for (int t = lo; t < hi; t++) {
        int byte = __ldg(&bytes[b * SS + t]);
        float4 v = reinterpret_cast<const float4*>(table)[byte * E4 + tid];
        acc0 = bf_add(acc0, bf_round(v.x));
        acc1 = bf_add(acc1, bf_round(v.y));
        acc2 = bf_add(acc2, bf_round(v.z));
        acc3 = bf_add(acc3, bf_round(v.w));
    }

    float o0, o1, o2, o3;
    if (cnt > 0) {
        float inv = (float)cnt;
        o0 = bf_round(acc0 / inv);
        o1 = bf_round(acc1 / inv);
        o2 = bf_round(acc2 / inv);
        o3 = bf_round(acc3 / inv);
    } else {
        o0 = o1 = o2 = o3 = 0.f;
    }
    __half2 h0 = __floats2half2_rn(o0, o1);
    __half2 h1 = __floats2half2_rn(o2, o3);
    uint2 pack;
    pack.x = *reinterpret_cast<uint32_t*>(&h0);
    pack.y = *reinterpret_cast<uint32_t*>(&h1);
    size_t row = (size_t)(b * PP + p);
    reinterpret_cast<uint2*>(g_A)[row * (EE / 4) + tid] = pack;
}

// ---------------------------------------------------------------------------
// Kernel 3: W prep — transpose [K,N] f32 -> [N,K] fp16 (tiled via SMEM)
// ---------------------------------------------------------------------------
__global__ __launch_bounds__(256) void wprep_kernel(const float* __restrict__ W) {
    __shared__ float t[32][33];
    int n0 = blockIdx.x * 32, k0 = blockIdx.y * 32;
    int tx = threadIdx.x, ty = threadIdx.y;   // block (32, 8)
    #pragma unroll
    for (int i = 0; i < 32; i += 8)
        t[ty + i][tx] = W[(size_t)(k0 + ty + i) * NN + n0 + tx];
    __syncthreads();
    #pragma unroll
    for (int i = 0; i < 32; i += 8)
        g_Wt[(size_t)(n0 + ty + i) * KK + k0 + tx] = __float2half_rn(t[tx][ty + i]);
}

// ---------------------------------------------------------------------------
// Kernel 4: fp16 tensor-core GEMM via mma.sync.m16n8k16.f32.f16.f16.f32
// C[M,N] = A[M,K] @ Wt[N,K]^T + bias, f32 accumulation
// CTA 128x256x64, 8 warps (2m x 4n), warp tile 64x64, 3-stage cp.async.
// ---------------------------------------------------------------------------
#define BM 128
#define BN 256
#define BK 64
#define STAGES 3
#define ROWB 144                         // 128B data + 16B pad (stride 9 units mod 8 = 1)
#define A_BYTES (BM * ROWB)              // 18432
#define B_BYTES (BN * ROWB)              // 36864
#define STAGE_BYTES (A_BYTES + B_BYTES)  // 55296
#define GEMM_SMEM (STAGES * STAGE_BYTES) // 165888

__device__ __forceinline__ uint32_t smem_u32(const void* p) {
    uint32_t a;
    asm("{ .reg .u64 t; cvta.to.shared.u64 t, %1; cvt.u32.u64 %0, t; }" : "=r"(a) : "l"(p));
    return a;
}
__device__ __forceinline__ void cp_async16(uint32_t saddr, const void* gaddr) {
    asm volatile("cp.async.cg.shared.global [%0], [%1], 16;\n" :: "r"(saddr), "l"(gaddr));
}
__device__ __forceinline__ void ldmatrix_x4(uint32_t* r, uint32_t addr) {
    asm volatile("ldmatrix.sync.aligned.m8n8.x4.shared.b16 {%0,%1,%2,%3}, [%4];"
                 : "=r"(r[0]), "=r"(r[1]), "=r"(r[2]), "=r"(r[3]) : "r"(addr));
}
__device__ __forceinline__ void mma_16816(float* c, const uint32_t* a, uint32_t b0, uint32_t b1) {
    asm volatile("mma.sync.aligned.m16n8k16.row.col.f32.f16.f16.f32 "
                 "{%0,%1,%2,%3}, {%4,%5,%6,%7}, {%8,%9}, {%0,%1,%2,%3};"
                 : "+f"(c[0]), "+f"(c[1]), "+f"(c[2]), "+f"(c[3])
                 : "r"(a[0]), "r"(a[1]), "r"(a[2]), "r"(a[3]), "r"(b0), "r"(b1));
}

__global__ __launch_bounds__(256, 1) void gemm_mma_kernel(const float* __restrict__ bias,
                                                          float* __restrict__ C) {
    extern __shared__ __align__(16) char smem[];
    uint32_t sbase = smem_u32(smem);

    const int tid = threadIdx.x;
    const int lane = tid & 31;
    const int wid = tid >> 5;
    const int wm = wid & 1;          // 0..1 -> m offset wm*64
    const int wn = wid >> 1;         // 0..3 -> n offset wn*64
    const int bm = blockIdx.y * BM;
    const int bn = blockIdx.x * BN;

    const __half* Ag = g_A  + (size_t)bm * KK;
    const __half* Bg = g_Wt + (size_t)bn * KK;

    // load: A 1024 16B-units (4/thread), B 2048 units (8/thread); row = u>>3, j = u&7
    auto load_stage = [&](int buf, int k0) {
        #pragma unroll
        for (int i = 0; i < 4; i++) {
            int unit = tid + i * 256;
            int r = unit >> 3, j = unit & 7;
            cp_async16(sbase + buf * STAGE_BYTES + r * ROWB + j * 16,
                       Ag + (size_t)r * KK + k0 + j * 8);
        }
        #pragma unroll
        for (int i = 0; i < 8; i++) {
            int unit = tid + i * 256;
            int r = unit >> 3, j = unit & 7;
            cp_async16(sbase + buf * STAGE_BYTES + A_BYTES + r * ROWB + j * 16,
                       Bg + (size_t)r * KK + k0 + j * 8);
        }
        asm volatile("cp.async.commit_group;\n");
    };

    float acc[4][8][4];
    #pragma unroll
    for (int mt = 0; mt < 4; mt++)
        #pragma unroll
        for (int nt = 0; nt < 8; nt++)
            #pragma unroll
            for (int q = 0; q < 4; q++) acc[mt][nt][q] = 0.f;

    const int NC = KK / BK;   // 16
    load_stage(0, 0);
    load_stage(1, BK);

    const int lrow = lane & 15;
    const int lcol16 = (lane >> 4) * 16;

    for (int c = 0; c < NC; c++) {
        if (c < NC - 1) {
            asm volatile("cp.async.wait_group 1;\n");
        } else {
            asm volatile("cp.async.wait_group 0;\n");
        }
        __syncthreads();   // stage c visible; readers of stage c-1 done

        if (c + 2 < NC)
            load_stage((c + 2) % STAGES, (c + 2) * BK);

        uint32_t Ab = sbase + (c % STAGES) * STAGE_BYTES;
        uint32_t Bb = Ab + A_BYTES;

        #pragma unroll
        for (int ks = 0; ks < 4; ks++) {
            uint32_t af[4][4];
            #pragma unroll
            for (int mt = 0; mt < 4; mt++)
                ldmatrix_x4(af[mt], Ab + (wm * 64 + mt * 16 + lrow) * ROWB + ks * 32 + lcol16);
            #pragma unroll
            for (int ntp = 0; ntp < 4; ntp++) {
                uint32_t bf[4];
                ldmatrix_x4(bf, Bb + (wn * 64 + ntp * 16 + lrow) * ROWB + ks * 32 + lcol16);
                #pragma unroll
                for (int mt = 0; mt < 4; mt++) {
                    mma_16816(acc[mt][2 * ntp + 0], af[mt], bf[0], bf[2]);
                    mma_16816(acc[mt][2 * ntp + 1], af[mt], bf[1], bf[3]);
                }
            }
        }
    }

    // Epilogue: m16n8 fragment -> C. row = lane/4 (+8 for regs 2,3), col = 2*(lane%4)
    const int er = lane >> 2;
    const int ec = (lane & 3) * 2;
    #pragma unroll
    for (int mt = 0; mt < 4; mt++) {
        #pragma unroll
        for (int nt = 0; nt < 8; nt++) {
            int n = bn + wn * 64 + nt * 8 + ec;
            float b0 = bias[n], b1 = bias[n + 1];
            int m0 = bm + wm * 64 + mt * 16 + er;
            float2 o0 = make_float2(acc[mt][nt][0] + b0, acc[mt][nt][1] + b1);
            float2 o1 = make_float2(acc[mt][nt][2] + b0, acc[mt][nt][3] + b1);
            *reinterpret_cast<float2*>(C + (size_t)m0 * NN + n) = o0;
            *reinterpret_cast<float2*>(C + (size_t)(m0 + 8) * NN + n) = o1;
        }
    }
}

// ---------------------------------------------------------------------------
// Launch — gather forked onto a side stream (captured fork/join) so its
// DRAM-bound writes overlap the L2/tensor-bound pool+GEMM chain.
// ---------------------------------------------------------------------------
extern "C" void kernel_launch(void* const* d_in, const int* in_sizes, int n_in,
                              void* d_out, int out_size) {
    const int*   bytes    = (const int*)d_in[0];
    const int*   pids     = (const int*)d_in[1];
    const float* table    = (const float*)d_in[2];
    const float* W        = (const float*)d_in[3];
    const float* bias     = (const float*)d_in[4];

    float* out         = (float*)d_out;
    float* byte_embeds = out;                                    // 8*4096*1024
    float* patch_embs  = out + (size_t)BB * SS * EE;             // 8*512*2048
    float* mask        = patch_embs + (size_t)BB * PP * GG;      // 8*512

    static cudaStream_t s_side = nullptr;
    static cudaEvent_t e_fork = nullptr, e_join = nullptr;
    if (s_side == nullptr) {
        cudaStreamCreateWithFlags(&s_side, cudaStreamNonBlocking);
        cudaEventCreateWithFlags(&e_fork, cudaEventDisableTiming);
        cudaEventCreateWithFlags(&e_join, cudaEventDisableTiming);
        cudaFuncSetAttribute(gemm_mma_kernel,
                             cudaFuncAttributeMaxDynamicSharedMemorySize, GEMM_SMEM);
    }

    // Fork: gather on side stream
    cudaEventRecord(e_fork, 0);
    cudaStreamWaitEvent(s_side, e_fork, 0);
    gather_kernel<<<BB * SS * (EE / 4) / 256, 256, 0, s_side>>>(bytes, table, byte_embeds);
    cudaEventRecord(e_join, s_side);

    // Main chain: wprep -> pool(+mask) -> GEMM
    wprep_kernel<<<dim3(NN / 32, KK / 32), dim3(32, 8)>>>(W);
    pool_kernel<<<dim3(PP, BB), 256>>>(bytes, pids, table, mask);
    gemm_mma_kernel<<<dim3(NN / BN, MM / BM), 256, GEMM_SMEM>>>(bias, patch_embs);

    // Join: launch stream completes only after gather is done
    cudaStreamWaitEvent(0, e_join, 0);
}

// round 7
// speedup vs baseline: 3.8878x; 1.0123x over previous
#include <cuda_runtime.h>
#include <cuda_bf16.h>
#include <cuda_fp16.h>
#include <stdint.h>

// Problem constants (fixed shapes from reference)
#define BB 8
#define SS 4096
#define EE 1024
#define GG 2048
#define VV 256
#define PP 512

#define MM (BB * PP)   // 4096 GEMM M
#define NN GG          // 2048 GEMM N
#define KK EE          // 1024 GEMM K

// Scratch (device globals — no allocation allowed)
__device__ __half g_A[(size_t)MM * KK];    // pooled patch embeddings, fp16 (exact bf16 values), [M,K]
__device__ __half g_Wt[(size_t)NN * KK];   // W transposed to [N,K], fp16

// ---------------------------------------------------------------------------
// bf16 emulation helpers
// ---------------------------------------------------------------------------
__device__ __forceinline__ float bf_round(float x) {
    return __bfloat162float(__float2bfloat16(x));
}
__device__ __forceinline__ float bf_add(float a_bf, float x_bf) {
    return bf_round(a_bf + x_bf);
}

// ---------------------------------------------------------------------------
// Kernel 1: byte_embeds = bf16(embed_table[bytes]) written as f32
// ---------------------------------------------------------------------------
__global__ void gather_kernel(const int* __restrict__ bytes,
                              const float* __restrict__ table,
                              float* __restrict__ out) {
    int idx = blockIdx.x * blockDim.x + threadIdx.x;       // float4 index
    const int E4 = EE / 4;
    int token = idx / E4;
    int e4 = idx - token * E4;
    int byte = __ldg(&bytes[token]);
    float4 v = reinterpret_cast<const float4*>(table)[byte * E4 + e4];
    v.x = bf_round(v.x);
    v.y = bf_round(v.y);
    v.z = bf_round(v.z);
    v.w = bf_round(v.w);
    reinterpret_cast<float4*>(out)[idx] = v;
}

// ---------------------------------------------------------------------------
// Kernel 2: patch pooling, exact bf16 sequential-accumulation semantics.
// Writes fp16 into g_A; fused patch_mask store.
// ---------------------------------------------------------------------------
__device__ __forceinline__ int lower_bound_dev(const int* __restrict__ a, int n, int v) {
    int lo = 0, hi = n;
    while (lo < hi) {
        int mid = (lo + hi) >> 1;
        if (a[mid] < v) lo = mid + 1; else hi = mid;
    }
    return lo;
}

__global__ __launch_bounds__(256) void pool_kernel(const int* __restrict__ bytes,
                                                   const int* __restrict__ patch_ids,
                                                   const float* __restrict__ table,
                                                   float* __restrict__ mask) {
    int p = blockIdx.x;            // patch 0..511
    int b = blockIdx.y;            // batch 0..7
    const int* pid = patch_ids + b * SS;

    if (threadIdx.x == 0) {
        int mx = __ldg(&pid[SS - 1]);
        mask[b * PP + p] = (p <= mx) ? 1.0f : 0.0f;
    }

    int lo = lower_bound_dev(pid, SS, p);
    int hi = lower_bound_dev(pid, SS, p + 1);
    int cnt = hi - lo;

    int tid = threadIdx.x;         // owns dims [tid*4, tid*4+4)
    float acc0 = 0.f, acc1 = 0.f, acc2 = 0.f, acc3 = 0.f;

    const int E4 = EE / 4;
    for (int t = lo; t < hi; t++) {
        int byte = __ldg(&bytes[b * SS + t]);
        float4 v = reinterpret_cast<const float4*>(table)[byte * E4 + tid];
        acc0 = bf_add(acc0, bf_round(v.x));
        acc1 = bf_add(acc1, bf_round(v.y));
        acc2 = bf_add(acc2, bf_round(v.z));
        acc3 = bf_add(acc3, bf_round(v.w));
    }

    float o0, o1, o2, o3;
    if (cnt > 0) {
        float inv = (float)cnt;
        o0 = bf_round(acc0 / inv);
        o1 = bf_round(acc1 / inv);
        o2 = bf_round(acc2 / inv);
        o3 = bf_round(acc3 / inv);
    } else {
        o0 = o1 = o2 = o3 = 0.f;
    }
    __half2 h0 = __floats2half2_rn(o0, o1);
    __half2 h1 = __floats2half2_rn(o2, o3);
    uint2 pack;
    pack.x = *reinterpret_cast<uint32_t*>(&h0);
    pack.y = *reinterpret_cast<uint32_t*>(&h1);
    size_t row = (size_t)(b * PP + p);
    reinterpret_cast<uint2*>(g_A)[row * (EE / 4) + tid] = pack;
}

// ---------------------------------------------------------------------------
// Kernel 3: W prep — transpose [K,N] f32 -> [N,K] fp16 (tiled via SMEM)
// ---------------------------------------------------------------------------
__global__ __launch_bounds__(256) void wprep_kernel(const float* __restrict__ W) {
    __shared__ float t[32][33];
    int n0 = blockIdx.x * 32, k0 = blockIdx.y * 32;
    int tx = threadIdx.x, ty = threadIdx.y;   // block (32, 8)
    #pragma unroll
    for (int i = 0; i < 32; i += 8)
        t[ty + i][tx] = W[(size_t)(k0 + ty + i) * NN + n0 + tx];
    __syncthreads();
    #pragma unroll
    for (int i = 0; i < 32; i += 8)
        g_Wt[(size_t)(n0 + ty + i) * KK + k0 + tx] = __float2half_rn(t[tx][ty + i]);
}

// ---------------------------------------------------------------------------
// Kernel 4: fp16 tensor-core GEMM via mma.sync.m16n8k16.f32.f16.f16.f32
// CTA 128x256x64, 8 warps (2m x 4n), warp tile 64x64, 3-stage cp.async,
// register double-buffered fragments (LDSM for ks+1 overlaps HMMA of ks).
// ---------------------------------------------------------------------------
#define BM 128
#define BN 256
#define BK 64
#define STAGES 3
#define ROWB 144                         // 128B data + 16B pad (16B-unit stride 9 mod 8 = 1)
#define A_BYTES (BM * ROWB)              // 18432
#define B_BYTES (BN * ROWB)              // 36864
#define STAGE_BYTES (A_BYTES + B_BYTES)  // 55296
#define GEMM_SMEM (STAGES * STAGE_BYTES) // 165888

__device__ __forceinline__ uint32_t smem_u32(const void* p) {
    uint32_t a;
    asm("{ .reg .u64 t; cvta.to.shared.u64 t, %1; cvt.u32.u64 %0, t; }" : "=r"(a) : "l"(p));
    return a;
}
__device__ __forceinline__ void cp_async16(uint32_t saddr, const void* gaddr) {
    asm volatile("cp.async.cg.shared.global [%0], [%1], 16;\n" :: "r"(saddr), "l"(gaddr));
}
__device__ __forceinline__ void ldmatrix_x4(uint32_t* r, uint32_t addr) {
    asm volatile("ldmatrix.sync.aligned.m8n8.x4.shared.b16 {%0,%1,%2,%3}, [%4];"
                 : "=r"(r[0]), "=r"(r[1]), "=r"(r[2]), "=r"(r[3]) : "r"(addr));
}
__device__ __forceinline__ void mma_16816(float* c, const uint32_t* a, uint32_t b0, uint32_t b1) {
    asm volatile("mma.sync.aligned.m16n8k16.row.col.f32.f16.f16.f32 "
                 "{%0,%1,%2,%3}, {%4,%5,%6,%7}, {%8,%9}, {%0,%1,%2,%3};"
                 : "+f"(c[0]), "+f"(c[1]), "+f"(c[2]), "+f"(c[3])
                 : "r"(a[0]), "r"(a[1]), "r"(a[2]), "r"(a[3]), "r"(b0), "r"(b1));
}

__global__ __launch_bounds__(256, 1) void gemm_mma_kernel(const float* __restrict__ bias,
                                                          float* __restrict__ C) {
    extern __shared__ __align__(16) char smem[];
    uint32_t sbase = smem_u32(smem);

    const int tid = threadIdx.x;
    const int lane = tid & 31;
    const int wid = tid >> 5;
    const int wm = wid & 1;          // 0..1 -> m offset wm*64
    const int wn = wid >> 1;         // 0..3 -> n offset wn*64
    const int bm = blockIdx.y * BM;
    const int bn = blockIdx.x * BN;

    const __half* Ag = g_A  + (size_t)bm * KK;
    const __half* Bg = g_Wt + (size_t)bn * KK;

    auto load_stage = [&](int buf, int k0) {
        #pragma unroll
        for (int i = 0; i < 4; i++) {
            int unit = tid + i * 256;
            int r = unit >> 3, j = unit & 7;
            cp_async16(sbase + buf * STAGE_BYTES + r * ROWB + j * 16,
                       Ag + (size_t)r * KK + k0 + j * 8);
        }
        #pragma unroll
        for (int i = 0; i < 8; i++) {
            int unit = tid + i * 256;
            int r = unit >> 3, j = unit & 7;
            cp_async16(sbase + buf * STAGE_BYTES + A_BYTES + r * ROWB + j * 16,
                       Bg + (size_t)r * KK + k0 + j * 8);
        }
        asm volatile("cp.async.commit_group;\n");
    };

    float acc[4][8][4];
    #pragma unroll
    for (int mt = 0; mt < 4; mt++)
        #pragma unroll
        for (int nt = 0; nt < 8; nt++)
            #pragma unroll
            for (int q = 0; q < 4; q++) acc[mt][nt][q] = 0.f;

    const int NC = KK / BK;   // 16
    load_stage(0, 0);
    load_stage(1, BK);

    const int lrow = lane & 15;
    const int lcol16 = (lane >> 4) * 16;

    // Double-buffered register fragments
    uint32_t af[2][4][4];
    uint32_t bfr[2][4][4];

    for (int c = 0; c < NC; c++) {
        if (c < NC - 1) {
            asm volatile("cp.async.wait_group 1;\n");
        } else {
            asm volatile("cp.async.wait_group 0;\n");
        }
        __syncthreads();   // stage c visible; readers of stage c-1 done

        if (c + 2 < NC)
            load_stage((c + 2) % STAGES, (c + 2) * BK);

        uint32_t Ab = sbase + (c % STAGES) * STAGE_BYTES;
        uint32_t Bb = Ab + A_BYTES;
        uint32_t Arow = Ab + (wm * 64 + lrow) * ROWB + lcol16;
        uint32_t Brow = Bb + (wn * 64 + lrow) * ROWB + lcol16;

        // prefetch ks=0 fragments
        #pragma unroll
        for (int mt = 0; mt < 4; mt++)
            ldmatrix_x4(af[0][mt], Arow + mt * 16 * ROWB);
        #pragma unroll
        for (int ntp = 0; ntp < 4; ntp++)
            ldmatrix_x4(bfr[0][ntp], Brow + ntp * 16 * ROWB);

        #pragma unroll
        for (int ks = 0; ks < 4; ks++) {
            const int cur = ks & 1;
            if (ks < 3) {
                const int nxt = cur ^ 1;
                #pragma unroll
                for (int mt = 0; mt < 4; mt++)
                    ldmatrix_x4(af[nxt][mt], Arow + mt * 16 * ROWB + (ks + 1) * 32);
                #pragma unroll
                for (int ntp = 0; ntp < 4; ntp++)
                    ldmatrix_x4(bfr[nxt][ntp], Brow + ntp * 16 * ROWB + (ks + 1) * 32);
            }
            #pragma unroll
            for (int ntp = 0; ntp < 4; ntp++) {
                #pragma unroll
                for (int mt = 0; mt < 4; mt++) {
                    mma_16816(acc[mt][2 * ntp + 0], af[cur][mt], bfr[cur][ntp][0], bfr[cur][ntp][2]);
                    mma_16816(acc[mt][2 * ntp + 1], af[cur][mt], bfr[cur][ntp][1], bfr[cur][ntp][3]);
                }
            }
        }
    }

    // Epilogue: m16n8 fragment -> C. row = lane/4 (+8 for regs 2,3), col = 2*(lane%4)
    const int er = lane >> 2;
    const int ec = (lane & 3) * 2;
    #pragma unroll
    for (int mt = 0; mt < 4; mt++) {
        #pragma unroll
        for (int nt = 0; nt < 8; nt++) {
            int n = bn + wn * 64 + nt * 8 + ec;
            float b0 = bias[n], b1 = bias[n + 1];
            int m0 = bm + wm * 64 + mt * 16 + er;
            float2 o0 = make_float2(acc[mt][nt][0] + b0, acc[mt][nt][1] + b1);
            float2 o1 = make_float2(acc[mt][nt][2] + b0, acc[mt][nt][3] + b1);
            *reinterpret_cast<float2*>(C + (size_t)m0 * NN + n) = o0;
            *reinterpret_cast<float2*>(C + (size_t)(m0 + 8) * NN + n) = o1;
        }
    }
}

// ---------------------------------------------------------------------------
// Launch — gather and wprep forked onto side streams; GEMM waits on wprep+pool.
// ---------------------------------------------------------------------------
extern "C" void kernel_launch(void* const* d_in, const int* in_sizes, int n_in,
                              void* d_out, int out_size) {
    const int*   bytes    = (const int*)d_in[0];
    const int*   pids     = (const int*)d_in[1];
    const float* table    = (const float*)d_in[2];
    const float* W        = (const float*)d_in[3];
    const float* bias     = (const float*)d_in[4];

    float* out         = (float*)d_out;
    float* byte_embeds = out;                                    // 8*4096*1024
    float* patch_embs  = out + (size_t)BB * SS * EE;             // 8*512*2048
    float* mask        = patch_embs + (size_t)BB * PP * GG;      // 8*512

    static cudaStream_t s_g = nullptr, s_w = nullptr;
    static cudaEvent_t e_fork = nullptr, e_g = nullptr, e_w = nullptr;
    if (s_g == nullptr) {
        cudaStreamCreateWithFlags(&s_g, cudaStreamNonBlocking);
        cudaStreamCreateWithFlags(&s_w, cudaStreamNonBlocking);
        cudaEventCreateWithFlags(&e_fork, cudaEventDisableTiming);
        cudaEventCreateWithFlags(&e_g, cudaEventDisableTiming);
        cudaEventCreateWithFlags(&e_w, cudaEventDisableTiming);
        cudaFuncSetAttribute(gemm_mma_kernel,
                             cudaFuncAttributeMaxDynamicSharedMemorySize, GEMM_SMEM);
    }

    // Fork
    cudaEventRecord(e_fork, 0);
    cudaStreamWaitEvent(s_g, e_fork, 0);
    cudaStreamWaitEvent(s_w, e_fork, 0);

    // Side stream 1: gather (independent of GEMM chain entirely)
    gather_kernel<<<BB * SS * (EE / 4) / 256, 256, 0, s_g>>>(bytes, table, byte_embeds);
    cudaEventRecord(e_g, s_g);

    // Side stream 2: W prep (feeds GEMM)
    wprep_kernel<<<dim3(NN / 32, KK / 32), dim3(32, 8), 0, s_w>>>(W);
    cudaEventRecord(e_w, s_w);

    // Main: pool(+mask) -> GEMM (after wprep)
    pool_kernel<<<dim3(PP, BB), 256>>>(bytes, pids, table, mask);
    cudaStreamWaitEvent(0, e_w, 0);
    gemm_mma_kernel<<<dim3(NN / BN, MM / BM), 256, GEMM_SMEM>>>(bias, patch_embs);

    // Join: gather must complete before the launch stream finishes
    cudaStreamWaitEvent(0, e_g, 0);
}

// round 8
// speedup vs baseline: 3.9236x; 1.0092x over previous
#include <cuda_runtime.h>
#include <cuda_bf16.h>
#include <cuda_fp16.h>
#include <stdint.h>

// Problem constants (fixed shapes from reference)
#define BB 8
#define SS 4096
#define EE 1024
#define GG 2048
#define VV 256
#define PP 512

#define MM (BB * PP)   // 4096 GEMM M
#define NN GG          // 2048 GEMM N
#define KK EE          // 1024 GEMM K

// Scratch (device globals — no allocation allowed)
__device__ __half g_A[(size_t)MM * KK];    // pooled patch embeddings, fp16 (exact bf16 values), [M,K]
__device__ __half g_Wt[(size_t)NN * KK];   // W transposed to [N,K], fp16

// ---------------------------------------------------------------------------
// bf16 emulation helpers
// ---------------------------------------------------------------------------
__device__ __forceinline__ float bf_round(float x) {
    return __bfloat162float(__float2bfloat16(x));
}
__device__ __forceinline__ float bf_add(float a_bf, float x_bf) {
    return bf_round(a_bf + x_bf);
}

// ---------------------------------------------------------------------------
// Kernel 1: byte_embeds = bf16(embed_table[bytes]) written as f32
// ---------------------------------------------------------------------------
__global__ void gather_kernel(const int* __restrict__ bytes,
                              const float* __restrict__ table,
                              float* __restrict__ out) {
    int idx = blockIdx.x * blockDim.x + threadIdx.x;       // float4 index
    const int E4 = EE / 4;
    int token = idx / E4;
    int e4 = idx - token * E4;
    int byte = __ldg(&bytes[token]);
    float4 v = reinterpret_cast<const float4*>(table)[byte * E4 + e4];
    v.x = bf_round(v.x);
    v.y = bf_round(v.y);
    v.z = bf_round(v.z);
    v.w = bf_round(v.w);
    reinterpret_cast<float4*>(out)[idx] = v;
}

// ---------------------------------------------------------------------------
// Kernel 2: patch pooling, exact bf16 sequential-accumulation semantics.
// Writes fp16 into g_A; fused patch_mask store.
// ---------------------------------------------------------------------------
__device__ __forceinline__ int lower_bound_dev(const int* __restrict__ a, int n, int v) {
    int lo = 0, hi = n;
    while (lo < hi) {
        int mid = (lo + hi) >> 1;
        if (a[mid] < v) lo = mid + 1; else hi = mid;
    }
    return lo;
}

__global__ __launch_bounds__(256) void pool_kernel(const int* __restrict__ bytes,
                                                   const int* __restrict__ patch_ids,
                                                   const float* __restrict__ table,
                                                   float* __restrict__ mask) {
    int p = blockIdx.x;            // patch 0..511
    int b = blockIdx.y;            // batch 0..7
    const int* pid = patch_ids + b * SS;

    if (threadIdx.x == 0) {
        int mx = __ldg(&pid[SS - 1]);
        mask[b * PP + p] = (p <= mx) ? 1.0f : 0.0f;
    }

    int lo = lower_bound_dev(pid, SS, p);
    int hi = lower_bound_dev(pid, SS, p + 1);
    int cnt = hi - lo;

    int tid = threadIdx.x;         // owns dims [tid*4, tid*4+4)
    float acc0 = 0.f, acc1 = 0.f, acc2 = 0.f, acc3 = 0.f;

    const int E4 = EE / 4;
    for (int t = lo; t < hi; t++) {
        int byte = __ldg(&bytes[b * SS + t]);
        float4 v = reinterpret_cast<const float4*>(table)[byte * E4 + tid];
        acc0 = bf_add(acc0, bf_round(v.x));
        acc1 = bf_add(acc1, bf_round(v.y));
        acc2 = bf_add(acc2, bf_round(v.z));
        acc3 = bf_add(acc3, bf_round(v.w));
    }

    float o0, o1, o2, o3;
    if (cnt > 0) {
        float inv = (float)cnt;
        o0 = bf_round(acc0 / inv);
        o1 = bf_round(acc1 / inv);
        o2 = bf_round(acc2 / inv);
        o3 = bf_round(acc3 / inv);
    } else {
        o0 = o1 = o2 = o3 = 0.f;
    }
    __half2 h0 = __floats2half2_rn(o0, o1);
    __half2 h1 = __floats2half2_rn(o2, o3);
    uint2 pack;
    pack.x = *reinterpret_cast<uint32_t*>(&h0);
    pack.y = *reinterpret_cast<uint32_t*>(&h1);
    size_t row = (size_t)(b * PP + p);
    reinterpret_cast<uint2*>(g_A)[row * (EE / 4) + tid] = pack;
}

// ---------------------------------------------------------------------------
// Kernel 3: W prep — transpose [K,N] f32 -> [N,K] fp16 (tiled via SMEM)
// ---------------------------------------------------------------------------
__global__ __launch_bounds__(256) void wprep_kernel(const float* __restrict__ W) {
    __shared__ float t[32][33];
    int n0 = blockIdx.x * 32, k0 = blockIdx.y * 32;
    int tx = threadIdx.x, ty = threadIdx.y;   // block (32, 8)
    #pragma unroll
    for (int i = 0; i < 32; i += 8)
        t[ty + i][tx] = W[(size_t)(k0 + ty + i) * NN + n0 + tx];
    __syncthreads();
    #pragma unroll
    for (int i = 0; i < 32; i += 8)
        g_Wt[(size_t)(n0 + ty + i) * KK + k0 + tx] = __float2half_rn(t[tx][ty + i]);
}

// ---------------------------------------------------------------------------
// Kernel 4: fp16 tensor-core GEMM via mma.sync.m16n8k16.f32.f16.f16.f32
// CTA 128x256x64, 512 threads / 16 warps (4m x 4n), warp tile 32x64,
// 3-stage cp.async. 64 acc regs/thread -> 4 warps per SMSP for latency hiding.
// ---------------------------------------------------------------------------
#define BM 128
#define BN 256
#define BK 64
#define STAGES 3
#define ROWB 144                         // 128B data + 16B pad (16B-unit stride 9 mod 8 = 1)
#define A_BYTES (BM * ROWB)              // 18432
#define B_BYTES (BN * ROWB)              // 36864
#define STAGE_BYTES (A_BYTES + B_BYTES)  // 55296
#define GEMM_SMEM (STAGES * STAGE_BYTES) // 165888
#define GTHREADS 512

__device__ __forceinline__ uint32_t smem_u32(const void* p) {
    uint32_t a;
    asm("{ .reg .u64 t; cvta.to.shared.u64 t, %1; cvt.u32.u64 %0, t; }" : "=r"(a) : "l"(p));
    return a;
}
__device__ __forceinline__ void cp_async16(uint32_t saddr, const void* gaddr) {
    asm volatile("cp.async.cg.shared.global [%0], [%1], 16;\n" :: "r"(saddr), "l"(gaddr));
}
__device__ __forceinline__ void ldmatrix_x4(uint32_t* r, uint32_t addr) {
    asm volatile("ldmatrix.sync.aligned.m8n8.x4.shared.b16 {%0,%1,%2,%3}, [%4];"
                 : "=r"(r[0]), "=r"(r[1]), "=r"(r[2]), "=r"(r[3]) : "r"(addr));
}
__device__ __forceinline__ void mma_16816(float* c, const uint32_t* a, uint32_t b0, uint32_t b1) {
    asm volatile("mma.sync.aligned.m16n8k16.row.col.f32.f16.f16.f32 "
                 "{%0,%1,%2,%3}, {%4,%5,%6,%7}, {%8,%9}, {%0,%1,%2,%3};"
                 : "+f"(c[0]), "+f"(c[1]), "+f"(c[2]), "+f"(c[3])
                 : "r"(a[0]), "r"(a[1]), "r"(a[2]), "r"(a[3]), "r"(b0), "r"(b1));
}

__global__ __launch_bounds__(GTHREADS, 1) void gemm_mma_kernel(const float* __restrict__ bias,
                                                               float* __restrict__ C) {
    extern __shared__ __align__(16) char smem[];
    uint32_t sbase = smem_u32(smem);

    const int tid = threadIdx.x;
    const int lane = tid & 31;
    const int wid = tid >> 5;        // 0..15
    const int wm = wid & 3;          // 0..3 -> m offset wm*32
    const int wn = wid >> 2;         // 0..3 -> n offset wn*64
    const int bm = blockIdx.y * BM;
    const int bn = blockIdx.x * BN;

    const __half* Ag = g_A  + (size_t)bm * KK;
    const __half* Bg = g_Wt + (size_t)bn * KK;

    // load: A 1024 16B-units (2/thread), B 2048 units (4/thread); row = u>>3, j = u&7
    auto load_stage = [&](int buf, int k0) {
        #pragma unroll
        for (int i = 0; i < 2; i++) {
            int unit = tid + i * GTHREADS;
            int r = unit >> 3, j = unit & 7;
            cp_async16(sbase + buf * STAGE_BYTES + r * ROWB + j * 16,
                       Ag + (size_t)r * KK + k0 + j * 8);
        }
        #pragma unroll
        for (int i = 0; i < 4; i++) {
            int unit = tid + i * GTHREADS;
            int r = unit >> 3, j = unit & 7;
            cp_async16(sbase + buf * STAGE_BYTES + A_BYTES + r * ROWB + j * 16,
                       Bg + (size_t)r * KK + k0 + j * 8);
        }
        asm volatile("cp.async.commit_group;\n");
    };

    float acc[2][8][4];
    #pragma unroll
    for (int mt = 0; mt < 2; mt++)
        #pragma unroll
        for (int nt = 0; nt < 8; nt++)
            #pragma unroll
            for (int q = 0; q < 4; q++) acc[mt][nt][q] = 0.f;

    const int NC = KK / BK;   // 16
    load_stage(0, 0);
    load_stage(1, BK);

    const int lrow = lane & 15;
    const int lcol16 = (lane >> 4) * 16;

    for (int c = 0; c < NC; c++) {
        if (c < NC - 1) {
            asm volatile("cp.async.wait_group 1;\n");
        } else {
            asm volatile("cp.async.wait_group 0;\n");
        }
        __syncthreads();   // stage c visible; readers of stage c-1 done

        if (c + 2 < NC)
            load_stage((c + 2) % STAGES, (c + 2) * BK);

        uint32_t Ab = sbase + (c % STAGES) * STAGE_BYTES;
        uint32_t Bb = Ab + A_BYTES;
        uint32_t Arow = Ab + (wm * 32 + lrow) * ROWB + lcol16;
        uint32_t Brow = Bb + (wn * 64 + lrow) * ROWB + lcol16;

        #pragma unroll
        for (int ks = 0; ks < 4; ks++) {
            uint32_t af[2][4];
            #pragma unroll
            for (int mt = 0; mt < 2; mt++)
                ldmatrix_x4(af[mt], Arow + mt * 16 * ROWB + ks * 32);
            #pragma unroll
            for (int ntp = 0; ntp < 4; ntp++) {
                uint32_t bf[4];
                ldmatrix_x4(bf, Brow + ntp * 16 * ROWB + ks * 32);
                #pragma unroll
                for (int mt = 0; mt < 2; mt++) {
                    mma_16816(acc[mt][2 * ntp + 0], af[mt], bf[0], bf[2]);
                    mma_16816(acc[mt][2 * ntp + 1], af[mt], bf[1], bf[3]);
                }
            }
        }
    }

    // Epilogue: m16n8 fragment -> C. row = lane/4 (+8 for regs 2,3), col = 2*(lane%4)
    const int er = lane >> 2;
    const int ec = (lane & 3) * 2;
    #pragma unroll
    for (int mt = 0; mt < 2; mt++) {
        #pragma unroll
        for (int nt = 0; nt < 8; nt++) {
            int n = bn + wn * 64 + nt * 8 + ec;
            float b0 = bias[n], b1 = bias[n + 1];
            int m0 = bm + wm * 32 + mt * 16 + er;
            float2 o0 = make_float2(acc[mt][nt][0] + b0, acc[mt][nt][1] + b1);
            float2 o1 = make_float2(acc[mt][nt][2] + b0, acc[mt][nt][3] + b1);
            *reinterpret_cast<float2*>(C + (size_t)m0 * NN + n) = o0;
            *reinterpret_cast<float2*>(C + (size_t)(m0 + 8) * NN + n) = o1;
        }
    }
}

// ---------------------------------------------------------------------------
// Launch — gather and wprep forked onto side streams; GEMM waits on wprep+pool.
// ---------------------------------------------------------------------------
extern "C" void kernel_launch(void* const* d_in, const int* in_sizes, int n_in,
                              void* d_out, int out_size) {
    const int*   bytes    = (const int*)d_in[0];
    const int*   pids     = (const int*)d_in[1];
    const float* table    = (const float*)d_in[2];
    const float* W        = (const float*)d_in[3];
    const float* bias     = (const float*)d_in[4];

    float* out         = (float*)d_out;
    float* byte_embeds = out;                                    // 8*4096*1024
    float* patch_embs  = out + (size_t)BB * SS * EE;             // 8*512*2048
    float* mask        = patch_embs + (size_t)BB * PP * GG;      // 8*512

    static cudaStream_t s_g = nullptr, s_w = nullptr;
    static cudaEvent_t e_fork = nullptr, e_g = nullptr, e_w = nullptr;
    if (s_g == nullptr) {
        cudaStreamCreateWithFlags(&s_g, cudaStreamNonBlocking);
        cudaStreamCreateWithFlags(&s_w, cudaStreamNonBlocking);
        cudaEventCreateWithFlags(&e_fork, cudaEventDisableTiming);
        cudaEventCreateWithFlags(&e_g, cudaEventDisableTiming);
        cudaEventCreateWithFlags(&e_w, cudaEventDisableTiming);
        cudaFuncSetAttribute(gemm_mma_kernel,
                             cudaFuncAttributeMaxDynamicSharedMemorySize, GEMM_SMEM);
    }

    // Fork
    cudaEventRecord(e_fork, 0);
    cudaStreamWaitEvent(s_g, e_fork, 0);
    cudaStreamWaitEvent(s_w, e_fork, 0);

    // Side stream 1: gather (independent of GEMM chain entirely)
    gather_kernel<<<BB * SS * (EE / 4) / 256, 256, 0, s_g>>>(bytes, table, byte_embeds);
    cudaEventRecord(e_g, s_g);

    // Side stream 2: W prep (feeds GEMM)
    wprep_kernel<<<dim3(NN / 32, KK / 32), dim3(32, 8), 0, s_w>>>(W);
    cudaEventRecord(e_w, s_w);

    // Main: pool(+mask) -> GEMM (after wprep)
    pool_kernel<<<dim3(PP, BB), 256>>>(bytes, pids, table, mask);
    cudaStreamWaitEvent(0, e_w, 0);
    gemm_mma_kernel<<<dim3(NN / BN, MM / BM), GTHREADS, GEMM_SMEM>>>(bias, patch_embs);

    // Join: gather must complete before the launch stream finishes
    cudaStreamWaitEvent(0, e_g, 0);
}

// round 9
// speedup vs baseline: 4.2272x; 1.0774x over previous
#include <cuda_runtime.h>
#include <cuda_bf16.h>
#include <cuda_fp16.h>
#include <stdint.h>

// Problem constants (fixed shapes from reference)
#define BB 8
#define SS 4096
#define EE 1024
#define GG 2048
#define VV 256
#define PP 512

#define MM (BB * PP)   // 4096 GEMM M
#define NN GG          // 2048 GEMM N
#define KK EE          // 1024 GEMM K

// Scratch (device globals — no allocation allowed)
__device__ __half g_A[(size_t)MM * KK];    // pooled patch embeddings, fp16 (exact bf16 values), [M,K]
__device__ __half g_Wt[(size_t)NN * KK];   // W transposed to [N,K], fp16

// ---------------------------------------------------------------------------
// bf16 emulation helpers
// ---------------------------------------------------------------------------
__device__ __forceinline__ float bf_round(float x) {
    return __bfloat162float(__float2bfloat16(x));
}
__device__ __forceinline__ float bf_add(float a_bf, float x_bf) {
    return bf_round(a_bf + x_bf);
}

// ---------------------------------------------------------------------------
// Kernel 1: byte_embeds = bf16(embed_table[bytes]) written as f32.
// Streaming stores (__stcs): output is write-once, keep it out of L2 so the
// concurrently-running GEMM keeps its operand reuse.
// ---------------------------------------------------------------------------
__global__ void gather_kernel(const int* __restrict__ bytes,
                              const float* __restrict__ table,
                              float* __restrict__ out) {
    int idx = blockIdx.x * blockDim.x + threadIdx.x;       // float4 index
    const int E4 = EE / 4;
    int token = idx / E4;
    int e4 = idx - token * E4;
    int byte = __ldg(&bytes[token]);
    float4 v = reinterpret_cast<const float4*>(table)[byte * E4 + e4];
    v.x = bf_round(v.x);
    v.y = bf_round(v.y);
    v.z = bf_round(v.z);
    v.w = bf_round(v.w);
    __stcs(reinterpret_cast<float4*>(out) + idx, v);
}

// ---------------------------------------------------------------------------
// Kernel 2: patch pooling, exact bf16 sequential-accumulation semantics.
// Writes fp16 into g_A; fused patch_mask store.
// ---------------------------------------------------------------------------
__device__ __forceinline__ int lower_bound_dev(const int* __restrict__ a, int n, int v) {
    int lo = 0, hi = n;
    while (lo < hi) {
        int mid = (lo + hi) >> 1;
        if (a[mid] < v) lo = mid + 1; else hi = mid;
    }
    return lo;
}

__global__ __launch_bounds__(256) void pool_kernel(const int* __restrict__ bytes,
                                                   const int* __restrict__ patch_ids,
                                                   const float* __restrict__ table,
                                                   float* __restrict__ mask) {
    int p = blockIdx.x;            // patch 0..511
    int b = blockIdx.y;            // batch 0..7
    const int* pid = patch_ids + b * SS;

    if (threadIdx.x == 0) {
        int mx = __ldg(&pid[SS - 1]);
        mask[b * PP + p] = (p <= mx) ? 1.0f : 0.0f;
    }

    int lo = lower_bound_dev(pid, SS, p);
    int hi = lower_bound_dev(pid, SS, p + 1);
    int cnt = hi - lo;

    int tid = threadIdx.x;         // owns dims [tid*4, tid*4+4)
    float acc0 = 0.f, acc1 = 0.f, acc2 = 0.f, acc3 = 0.f;

    const int E4 = EE / 4;
    for (int t = lo; t < hi; t++) {
        int byte = __ldg(&bytes[b * SS + t]);
        float4 v = reinterpret_cast<const float4*>(table)[byte * E4 + tid];
        acc0 = bf_add(acc0, bf_round(v.x));
        acc1 = bf_add(acc1, bf_round(v.y));
        acc2 = bf_add(acc2, bf_round(v.z));
        acc3 = bf_add(acc3, bf_round(v.w));
    }

    float o0, o1, o2, o3;
    if (cnt > 0) {
        float inv = (float)cnt;
        o0 = bf_round(acc0 / inv);
        o1 = bf_round(acc1 / inv);
        o2 = bf_round(acc2 / inv);
        o3 = bf_round(acc3 / inv);
    } else {
        o0 = o1 = o2 = o3 = 0.f;
    }
    __half2 h0 = __floats2half2_rn(o0, o1);
    __half2 h1 = __floats2half2_rn(o2, o3);
    uint2 pack;
    pack.x = *reinterpret_cast<uint32_t*>(&h0);
    pack.y = *reinterpret_cast<uint32_t*>(&h1);
    size_t row = (size_t)(b * PP + p);
    reinterpret_cast<uint2*>(g_A)[row * (EE / 4) + tid] = pack;
}

// ---------------------------------------------------------------------------
// Kernel 3: W prep — transpose [K,N] f32 -> [N,K] fp16 (tiled via SMEM)
// ---------------------------------------------------------------------------
__global__ __launch_bounds__(256) void wprep_kernel(const float* __restrict__ W) {
    __shared__ float t[32][33];
    int n0 = blockIdx.x * 32, k0 = blockIdx.y * 32;
    int tx = threadIdx.x, ty = threadIdx.y;   // block (32, 8)
    #pragma unroll
    for (int i = 0; i < 32; i += 8)
        t[ty + i][tx] = W[(size_t)(k0 + ty + i) * NN + n0 + tx];
    __syncthreads();
    #pragma unroll
    for (int i = 0; i < 32; i += 8)
        g_Wt[(size_t)(n0 + ty + i) * KK + k0 + tx] = __float2half_rn(t[tx][ty + i]);
}

// ---------------------------------------------------------------------------
// Kernel 4: fp16 tensor-core GEMM via mma.sync.m16n8k16.f32.f16.f16.f32
// CTA 128x256x64, 512 threads / 16 warps (4m x 4n), warp tile 32x64,
// 3-stage cp.async. (unchanged from R8 — isolating the scheduling change)
// ---------------------------------------------------------------------------
#define BM 128
#define BN 256
#define BK 64
#define STAGES 3
#define ROWB 144                         // 128B data + 16B pad (16B-unit stride 9 mod 8 = 1)
#define A_BYTES (BM * ROWB)              // 18432
#define B_BYTES (BN * ROWB)              // 36864
#define STAGE_BYTES (A_BYTES + B_BYTES)  // 55296
#define GEMM_SMEM (STAGES * STAGE_BYTES) // 165888
#define GTHREADS 512

__device__ __forceinline__ uint32_t smem_u32(const void* p) {
    uint32_t a;
    asm("{ .reg .u64 t; cvta.to.shared.u64 t, %1; cvt.u32.u64 %0, t; }" : "=r"(a) : "l"(p));
    return a;
}
__device__ __forceinline__ void cp_async16(uint32_t saddr, const void* gaddr) {
    asm volatile("cp.async.cg.shared.global [%0], [%1], 16;\n" :: "r"(saddr), "l"(gaddr));
}
__device__ __forceinline__ void ldmatrix_x4(uint32_t* r, uint32_t addr) {
    asm volatile("ldmatrix.sync.aligned.m8n8.x4.shared.b16 {%0,%1,%2,%3}, [%4];"
                 : "=r"(r[0]), "=r"(r[1]), "=r"(r[2]), "=r"(r[3]) : "r"(addr));
}
__device__ __forceinline__ void mma_16816(float* c, const uint32_t* a, uint32_t b0, uint32_t b1) {
    asm volatile("mma.sync.aligned.m16n8k16.row.col.f32.f16.f16.f32 "
                 "{%0,%1,%2,%3}, {%4,%5,%6,%7}, {%8,%9}, {%0,%1,%2,%3};"
                 : "+f"(c[0]), "+f"(c[1]), "+f"(c[2]), "+f"(c[3])
                 : "r"(a[0]), "r"(a[1]), "r"(a[2]), "r"(a[3]), "r"(b0), "r"(b1));
}

__global__ __launch_bounds__(GTHREADS, 1) void gemm_mma_kernel(const float* __restrict__ bias,
                                                               float* __restrict__ C) {
    extern __shared__ __align__(16) char smem[];
    uint32_t sbase = smem_u32(smem);

    const int tid = threadIdx.x;
    const int lane = tid & 31;
    const int wid = tid >> 5;        // 0..15
    const int wm = wid & 3;          // 0..3 -> m offset wm*32
    const int wn = wid >> 2;         // 0..3 -> n offset wn*64
    const int bm = blockIdx.y * BM;
    const int bn = blockIdx.x * BN;

    const __half* Ag = g_A  + (size_t)bm * KK;
    const __half* Bg = g_Wt + (size_t)bn * KK;

    auto load_stage = [&](int buf, int k0) {
        #pragma unroll
        for (int i = 0; i < 2; i++) {
            int unit = tid + i * GTHREADS;
            int r = unit >> 3, j = unit & 7;
            cp_async16(sbase + buf * STAGE_BYTES + r * ROWB + j * 16,
                       Ag + (size_t)r * KK + k0 + j * 8);
        }
        #pragma unroll
        for (int i = 0; i < 4; i++) {
            int unit = tid + i * GTHREADS;
            int r = unit >> 3, j = unit & 7;
            cp_async16(sbase + buf * STAGE_BYTES + A_BYTES + r * ROWB + j * 16,
                       Bg + (size_t)r * KK + k0 + j * 8);
        }
        asm volatile("cp.async.commit_group;\n");
    };

    float acc[2][8][4];
    #pragma unroll
    for (int mt = 0; mt < 2; mt++)
        #pragma unroll
        for (int nt = 0; nt < 8; nt++)
            #pragma unroll
            for (int q = 0; q < 4; q++) acc[mt][nt][q] = 0.f;

    const int NC = KK / BK;   // 16
    load_stage(0, 0);
    load_stage(1, BK);

    const int lrow = lane & 15;
    const int lcol16 = (lane >> 4) * 16;

    for (int c = 0; c < NC; c++) {
        if (c < NC - 1) {
            asm volatile("cp.async.wait_group 1;\n");
        } else {
            asm volatile("cp.async.wait_group 0;\n");
        }
        __syncthreads();   // stage c visible; readers of stage c-1 done

        if (c + 2 < NC)
            load_stage((c + 2) % STAGES, (c + 2) * BK);

        uint32_t Ab = sbase + (c % STAGES) * STAGE_BYTES;
        uint32_t Bb = Ab + A_BYTES;
        uint32_t Arow = Ab + (wm * 32 + lrow) * ROWB + lcol16;
        uint32_t Brow = Bb + (wn * 64 + lrow) * ROWB + lcol16;

        #pragma unroll
        for (int ks = 0; ks < 4; ks++) {
            uint32_t af[2][4];
            #pragma unroll
            for (int mt = 0; mt < 2; mt++)
                ldmatrix_x4(af[mt], Arow + mt * 16 * ROWB + ks * 32);
            #pragma unroll
            for (int ntp = 0; ntp < 4; ntp++) {
                uint32_t bf[4];
                ldmatrix_x4(bf, Brow + ntp * 16 * ROWB + ks * 32);
                #pragma unroll
                for (int mt = 0; mt < 2; mt++) {
                    mma_16816(acc[mt][2 * ntp + 0], af[mt], bf[0], bf[2]);
                    mma_16816(acc[mt][2 * ntp + 1], af[mt], bf[1], bf[3]);
                }
            }
        }
    }

    // Epilogue: m16n8 fragment -> C. row = lane/4 (+8 for regs 2,3), col = 2*(lane%4)
    const int er = lane >> 2;
    const int ec = (lane & 3) * 2;
    #pragma unroll
    for (int mt = 0; mt < 2; mt++) {
        #pragma unroll
        for (int nt = 0; nt < 8; nt++) {
            int n = bn + wn * 64 + nt * 8 + ec;
            float b0 = bias[n], b1 = bias[n + 1];
            int m0 = bm + wm * 32 + mt * 16 + er;
            float2 o0 = make_float2(acc[mt][nt][0] + b0, acc[mt][nt][1] + b1);
            float2 o1 = make_float2(acc[mt][nt][2] + b0, acc[mt][nt][3] + b1);
            *reinterpret_cast<float2*>(C + (size_t)m0 * NN + n) = o0;
            *reinterpret_cast<float2*>(C + (size_t)(m0 + 8) * NN + n) = o1;
        }
    }
}

// ---------------------------------------------------------------------------
// Launch — scheduling for backfill overlap:
//   main:  pool(+mask) ──────────► GEMM (waits wprep)
//   s_w:   wprep (concurrent with pool)
//   s_g:   gather, gated on pool completion, so its small CTAs backfill the
//          thread slots the 1-CTA/SM GEMM leaves idle (DRAM-write-bound work
//          overlapping L2/tensor-bound work).
// ---------------------------------------------------------------------------
extern "C" void kernel_launch(void* const* d_in, const int* in_sizes, int n_in,
                              void* d_out, int out_size) {
    const int*   bytes    = (const int*)d_in[0];
    const int*   pids     = (const int*)d_in[1];
    const float* table    = (const float*)d_in[2];
    const float* W        = (const float*)d_in[3];
    const float* bias     = (const float*)d_in[4];

    float* out         = (float*)d_out;
    float* byte_embeds = out;                                    // 8*4096*1024
    float* patch_embs  = out + (size_t)BB * SS * EE;             // 8*512*2048
    float* mask        = patch_embs + (size_t)BB * PP * GG;      // 8*512

    static cudaStream_t s_g = nullptr, s_w = nullptr;
    static cudaEvent_t e_fork = nullptr, e_p = nullptr, e_g = nullptr, e_w = nullptr;
    if (s_g == nullptr) {
        cudaStreamCreateWithFlags(&s_g, cudaStreamNonBlocking);
        cudaStreamCreateWithFlags(&s_w, cudaStreamNonBlocking);
        cudaEventCreateWithFlags(&e_fork, cudaEventDisableTiming);
        cudaEventCreateWithFlags(&e_p, cudaEventDisableTiming);
        cudaEventCreateWithFlags(&e_g, cudaEventDisableTiming);
        cudaEventCreateWithFlags(&e_w, cudaEventDisableTiming);
        cudaFuncSetAttribute(gemm_mma_kernel,
                             cudaFuncAttributeMaxDynamicSharedMemorySize, GEMM_SMEM);
    }

    // Fork: wprep runs concurrently with pool
    cudaEventRecord(e_fork, 0);
    cudaStreamWaitEvent(s_w, e_fork, 0);
    wprep_kernel<<<dim3(NN / 32, KK / 32), dim3(32, 8), 0, s_w>>>(W);
    cudaEventRecord(e_w, s_w);

    // Main: pool(+mask)
    pool_kernel<<<dim3(PP, BB), 256>>>(bytes, pids, table, mask);
    cudaEventRecord(e_p, 0);

    // Side: gather gated on pool so it backfills during the GEMM
    cudaStreamWaitEvent(s_g, e_p, 0);
    gather_kernel<<<BB * SS * (EE / 4) / 256, 256, 0, s_g>>>(bytes, table, byte_embeds);
    cudaEventRecord(e_g, s_g);

    // Main: GEMM (after wprep + pool)
    cudaStreamWaitEvent(0, e_w, 0);
    gemm_mma_kernel<<<dim3(NN / BN, MM / BM), GTHREADS, GEMM_SMEM>>>(bias, patch_embs);

    // Join: gather must complete before the launch stream finishes
    cudaStreamWaitEvent(0, e_g, 0);
}

// round 10
// speedup vs baseline: 4.5018x; 1.0650x over previous
#include <cuda_runtime.h>
#include <cuda_bf16.h>
#include <cuda_fp16.h>
#include <stdint.h>

// Problem constants (fixed shapes from reference)
#define BB 8
#define SS 4096
#define EE 1024
#define GG 2048
#define VV 256
#define PP 512

#define MM (BB * PP)   // 4096 GEMM M
#define NN GG          // 2048 GEMM N
#define KK EE          // 1024 GEMM K

// Scratch (device globals — no allocation allowed)
__device__ __half g_A[(size_t)MM * KK];    // pooled patch embeddings, fp16 (exact bf16 values), [M,K]
__device__ __half g_Wt[(size_t)NN * KK];   // W transposed to [N,K], fp16

// ---------------------------------------------------------------------------
// bf16 emulation helpers
// ---------------------------------------------------------------------------
__device__ __forceinline__ float bf_round(float x) {
    return __bfloat162float(__float2bfloat16(x));
}
__device__ __forceinline__ float bf_add(float a_bf, float x_bf) {
    return bf_round(a_bf + x_bf);
}

// ---------------------------------------------------------------------------
// Kernel 1: patch pooling, exact bf16 sequential-accumulation semantics.
// Writes fp16 into g_A; fused patch_mask store.
// ---------------------------------------------------------------------------
__device__ __forceinline__ int lower_bound_dev(const int* __restrict__ a, int n, int v) {
    int lo = 0, hi = n;
    while (lo < hi) {
        int mid = (lo + hi) >> 1;
        if (a[mid] < v) lo = mid + 1; else hi = mid;
    }
    return lo;
}

__global__ __launch_bounds__(256) void pool_kernel(const int* __restrict__ bytes,
                                                   const int* __restrict__ patch_ids,
                                                   const float* __restrict__ table,
                                                   float* __restrict__ mask) {
    int p = blockIdx.x;            // patch 0..511
    int b = blockIdx.y;            // batch 0..7
    const int* pid = patch_ids + b * SS;

    if (threadIdx.x == 0) {
        int mx = __ldg(&pid[SS - 1]);
        mask[b * PP + p] = (p <= mx) ? 1.0f : 0.0f;
    }

    int lo = lower_bound_dev(pid, SS, p);
    int hi = lower_bound_dev(pid, SS, p + 1);
    int cnt = hi - lo;

    int tid = threadIdx.x;         // owns dims [tid*4, tid*4+4)
    float acc0 = 0.f, acc1 = 0.f, acc2 = 0.f, acc3 = 0.f;

    const int E4 = EE / 4;
    for (int t = lo; t < hi; t++) {
        int byte = __ldg(&bytes[b * SS + t]);
        float4 v = reinterpret_cast<const float4*>(table)[byte * E4 + tid];
        acc0 = bf_add(acc0, bf_round(v.x));
        acc1 = bf_add(acc1, bf_round(v.y));
        acc2 = bf_add(acc2, bf_round(v.z));
        acc3 = bf_add(acc3, bf_round(v.w));
    }

    float o0, o1, o2, o3;
    if (cnt > 0) {
        float inv = (float)cnt;
        o0 = bf_round(acc0 / inv);
        o1 = bf_round(acc1 / inv);
        o2 = bf_round(acc2 / inv);
        o3 = bf_round(acc3 / inv);
    } else {
        o0 = o1 = o2 = o3 = 0.f;
    }
    __half2 h0 = __floats2half2_rn(o0, o1);
    __half2 h1 = __floats2half2_rn(o2, o3);
    uint2 pack;
    pack.x = *reinterpret_cast<uint32_t*>(&h0);
    pack.y = *reinterpret_cast<uint32_t*>(&h1);
    size_t row = (size_t)(b * PP + p);
    reinterpret_cast<uint2*>(g_A)[row * (EE / 4) + tid] = pack;
}

// ---------------------------------------------------------------------------
// Kernel 2: W prep — transpose [K,N] f32 -> [N,K] fp16 (tiled via SMEM)
// ---------------------------------------------------------------------------
__global__ __launch_bounds__(256) void wprep_kernel(const float* __restrict__ W) {
    __shared__ float t[32][33];
    int n0 = blockIdx.x * 32, k0 = blockIdx.y * 32;
    int tx = threadIdx.x, ty = threadIdx.y;   // block (32, 8)
    #pragma unroll
    for (int i = 0; i < 32; i += 8)
        t[ty + i][tx] = W[(size_t)(k0 + ty + i) * NN + n0 + tx];
    __syncthreads();
    #pragma unroll
    for (int i = 0; i < 32; i += 8)
        g_Wt[(size_t)(n0 + ty + i) * KK + k0 + tx] = __float2half_rn(t[tx][ty + i]);
}

// ---------------------------------------------------------------------------
// Kernel 3: FUSED fp16 tensor-core GEMM + byte_embeds gather.
// GEMM: CTA 128x256x64, 512 thr / 16 warps (4m x 4n), 3-stage cp.async.
// The GEMM is HMMA-issue-bound (~16cyc/HMMA/SMSP ceiling); LSU + issue slots
// are idle, so each CTA also streams its 32768-float4 slice of the gather
// (4 float4/thread/chunk), pipelined in pairs so LDG latency hides under MMAs.
// ---------------------------------------------------------------------------
#define BM 128
#define BN 256
#define BK 64
#define STAGES 3
#define ROWB 144                         // 128B data + 16B pad (16B-unit stride 9 mod 8 = 1)
#define A_BYTES (BM * ROWB)              // 18432
#define B_BYTES (BN * ROWB)              // 36864
#define STAGE_BYTES (A_BYTES + B_BYTES)  // 55296
#define GEMM_SMEM (STAGES * STAGE_BYTES) // 165888
#define GTHREADS 512
#define G_PER_CTA 32768                  // float4s of gather per CTA (8.4M / 256)
#define G_PER_CHUNK 2048                 // per chunk (G_PER_CTA / 16)

__device__ __forceinline__ uint32_t smem_u32(const void* p) {
    uint32_t a;
    asm("{ .reg .u64 t; cvta.to.shared.u64 t, %1; cvt.u32.u64 %0, t; }" : "=r"(a) : "l"(p));
    return a;
}
__device__ __forceinline__ void cp_async16(uint32_t saddr, const void* gaddr) {
    asm volatile("cp.async.cg.shared.global [%0], [%1], 16;\n" :: "r"(saddr), "l"(gaddr));
}
__device__ __forceinline__ void ldmatrix_x4(uint32_t* r, uint32_t addr) {
    asm volatile("ldmatrix.sync.aligned.m8n8.x4.shared.b16 {%0,%1,%2,%3}, [%4];"
                 : "=r"(r[0]), "=r"(r[1]), "=r"(r[2]), "=r"(r[3]) : "r"(addr));
}
__device__ __forceinline__ void mma_16816(float* c, const uint32_t* a, uint32_t b0, uint32_t b1) {
    asm volatile("mma.sync.aligned.m16n8k16.row.col.f32.f16.f16.f32 "
                 "{%0,%1,%2,%3}, {%4,%5,%6,%7}, {%8,%9}, {%0,%1,%2,%3};"
                 : "+f"(c[0]), "+f"(c[1]), "+f"(c[2]), "+f"(c[3])
                 : "r"(a[0]), "r"(a[1]), "r"(a[2]), "r"(a[3]), "r"(b0), "r"(b1));
}

__device__ __forceinline__ float4 gfetch(const int* __restrict__ bytes,
                                         const float4* __restrict__ t4, int u) {
    int tok = u >> 8;          // E/4 = 256 float4 per row
    int e4 = u & 255;
    return t4[__ldg(&bytes[tok]) * 256 + e4];
}
__device__ __forceinline__ void gstore(float4* out4, int u, float4 v) {
    v.x = bf_round(v.x);
    v.y = bf_round(v.y);
    v.z = bf_round(v.z);
    v.w = bf_round(v.w);
    __stcs(out4 + u, v);       // streaming: keep dead-on-arrival writes out of L2
}

__global__ __launch_bounds__(GTHREADS, 1) void gemm_mma_kernel(const float* __restrict__ bias,
                                                               float* __restrict__ C,
                                                               const int* __restrict__ bytes,
                                                               const float* __restrict__ table,
                                                               float* __restrict__ gout) {
    extern __shared__ __align__(16) char smem[];
    uint32_t sbase = smem_u32(smem);

    const int tid = threadIdx.x;
    const int lane = tid & 31;
    const int wid = tid >> 5;        // 0..15
    const int wm = wid & 3;          // 0..3 -> m offset wm*32
    const int wn = wid >> 2;         // 0..3 -> n offset wn*64
    const int bm = blockIdx.y * BM;
    const int bn = blockIdx.x * BN;
    const int cta = blockIdx.y * gridDim.x + blockIdx.x;   // 0..255

    const __half* Ag = g_A  + (size_t)bm * KK;
    const __half* Bg = g_Wt + (size_t)bn * KK;
    const float4* t4 = reinterpret_cast<const float4*>(table);
    float4* gout4 = reinterpret_cast<float4*>(gout);

    auto load_stage = [&](int buf, int k0) {
        #pragma unroll
        for (int i = 0; i < 2; i++) {
            int unit = tid + i * GTHREADS;
            int r = unit >> 3, j = unit & 7;
            cp_async16(sbase + buf * STAGE_BYTES + r * ROWB + j * 16,
                       Ag + (size_t)r * KK + k0 + j * 8);
        }
        #pragma unroll
        for (int i = 0; i < 4; i++) {
            int unit = tid + i * GTHREADS;
            int r = unit >> 3, j = unit & 7;
            cp_async16(sbase + buf * STAGE_BYTES + A_BYTES + r * ROWB + j * 16,
                       Bg + (size_t)r * KK + k0 + j * 8);
        }
        asm volatile("cp.async.commit_group;\n");
    };

    float acc[2][8][4];
    #pragma unroll
    for (int mt = 0; mt < 2; mt++)
        #pragma unroll
        for (int nt = 0; nt < 8; nt++)
            #pragma unroll
            for (int q = 0; q < 4; q++) acc[mt][nt][q] = 0.f;

    const int NC = KK / BK;   // 16
    load_stage(0, 0);
    load_stage(1, BK);

    const int lrow = lane & 15;
    const int lcol16 = (lane >> 4) * 16;

    for (int c = 0; c < NC; c++) {
        if (c < NC - 1) {
            asm volatile("cp.async.wait_group 1;\n");
        } else {
            asm volatile("cp.async.wait_group 0;\n");
        }
        __syncthreads();   // stage c visible; readers of stage c-1 done

        if (c + 2 < NC)
            load_stage((c + 2) % STAGES, (c + 2) * BK);

        // --- gather slice for this chunk: 4 float4/thread, pipelined pairs ---
        const int gu = cta * G_PER_CTA + c * G_PER_CHUNK + tid;
        float4 gv0 = gfetch(bytes, t4, gu);
        float4 gv1 = gfetch(bytes, t4, gu + GTHREADS);
        float4 gv2, gv3;

        uint32_t Ab = sbase + (c % STAGES) * STAGE_BYTES;
        uint32_t Bb = Ab + A_BYTES;
        uint32_t Arow = Ab + (wm * 32 + lrow) * ROWB + lcol16;
        uint32_t Brow = Bb + (wn * 64 + lrow) * ROWB + lcol16;

        #pragma unroll
        for (int ks = 0; ks < 4; ks++) {
            if (ks == 2) {
                // pair 1 stores (LDG issued ~2 k-steps ago), pair 2 loads
                gstore(gout4, gu, gv0);
                gstore(gout4, gu + GTHREADS, gv1);
                gv2 = gfetch(bytes, t4, gu + 2 * GTHREADS);
                gv3 = gfetch(bytes, t4, gu + 3 * GTHREADS);
            }
            uint32_t af[2][4];
            #pragma unroll
            for (int mt = 0; mt < 2; mt++)
                ldmatrix_x4(af[mt], Arow + mt * 16 * ROWB + ks * 32);
            #pragma unroll
            for (int ntp = 0; ntp < 4; ntp++) {
                uint32_t bf[4];
                ldmatrix_x4(bf, Brow + ntp * 16 * ROWB + ks * 32);
                #pragma unroll
                for (int mt = 0; mt < 2; mt++) {
                    mma_16816(acc[mt][2 * ntp + 0], af[mt], bf[0], bf[2]);
                    mma_16816(acc[mt][2 * ntp + 1], af[mt], bf[1], bf[3]);
                }
            }
        }
        // pair 2 stores (covered by the last 2 k-steps of MMA)
        gstore(gout4, gu + 2 * GTHREADS, gv2);
        gstore(gout4, gu + 3 * GTHREADS, gv3);
    }

    // Epilogue: m16n8 fragment -> C. row = lane/4 (+8 for regs 2,3), col = 2*(lane%4)
    const int er = lane >> 2;
    const int ec = (lane & 3) * 2;
    #pragma unroll
    for (int mt = 0; mt < 2; mt++) {
        #pragma unroll
        for (int nt = 0; nt < 8; nt++) {
            int n = bn + wn * 64 + nt * 8 + ec;
            float b0 = bias[n], b1 = bias[n + 1];
            int m0 = bm + wm * 32 + mt * 16 + er;
            float2 o0 = make_float2(acc[mt][nt][0] + b0, acc[mt][nt][1] + b1);
            float2 o1 = make_float2(acc[mt][nt][2] + b0, acc[mt][nt][3] + b1);
            *reinterpret_cast<float2*>(C + (size_t)m0 * NN + n) = o0;
            *reinterpret_cast<float2*>(C + (size_t)(m0 + 8) * NN + n) = o1;
        }
    }
}

// ---------------------------------------------------------------------------
// Launch — wprep ∥ pool, then the fused GEMM+gather kernel.
// ---------------------------------------------------------------------------
extern "C" void kernel_launch(void* const* d_in, const int* in_sizes, int n_in,
                              void* d_out, int out_size) {
    const int*   bytes    = (const int*)d_in[0];
    const int*   pids     = (const int*)d_in[1];
    const float* table    = (const float*)d_in[2];
    const float* W        = (const float*)d_in[3];
    const float* bias     = (const float*)d_in[4];

    float* out         = (float*)d_out;
    float* byte_embeds = out;                                    // 8*4096*1024
    float* patch_embs  = out + (size_t)BB * SS * EE;             // 8*512*2048
    float* mask        = patch_embs + (size_t)BB * PP * GG;      // 8*512

    static cudaStream_t s_w = nullptr;
    static cudaEvent_t e_fork = nullptr, e_w = nullptr;
    if (s_w == nullptr) {
        cudaStreamCreateWithFlags(&s_w, cudaStreamNonBlocking);
        cudaEventCreateWithFlags(&e_fork, cudaEventDisableTiming);
        cudaEventCreateWithFlags(&e_w, cudaEventDisableTiming);
        cudaFuncSetAttribute(gemm_mma_kernel,
                             cudaFuncAttributeMaxDynamicSharedMemorySize, GEMM_SMEM);
    }

    // Fork: wprep runs concurrently with pool
    cudaEventRecord(e_fork, 0);
    cudaStreamWaitEvent(s_w, e_fork, 0);
    wprep_kernel<<<dim3(NN / 32, KK / 32), dim3(32, 8), 0, s_w>>>(W);
    cudaEventRecord(e_w, s_w);

    // Main: pool(+mask)
    pool_kernel<<<dim3(PP, BB), 256>>>(bytes, pids, table, mask);

    // Main: fused GEMM + gather (after wprep + pool)
    cudaStreamWaitEvent(0, e_w, 0);
    gemm_mma_kernel<<<dim3(NN / BN, MM / BM), GTHREADS, GEMM_SMEM>>>(
        bias, patch_embs, bytes, table, byte_embeds);
}

// round 11
// speedup vs baseline: 4.5342x; 1.0072x over previous
#include <cuda_runtime.h>
#include <cuda_bf16.h>
#include <cuda_fp16.h>
#include <stdint.h>

// Problem constants (fixed shapes from reference)
#define BB 8
#define SS 4096
#define EE 1024
#define GG 2048
#define VV 256
#define PP 512

#define MM (BB * PP)   // 4096 GEMM M
#define NN GG          // 2048 GEMM N
#define KK EE          // 1024 GEMM K

// Scratch (device globals — no allocation allowed)
__device__ __half g_A[(size_t)MM * KK];    // pooled patch embeddings, fp16 (exact bf16 values), [M,K]
__device__ __half g_Wt[(size_t)NN * KK];   // W transposed to [N,K], fp16
__device__ uint2  g_tb2[(size_t)VV * EE / 4];  // bf16 table, 4 bf16 per uint2 (512 KB)

// ---------------------------------------------------------------------------
// bf16 emulation helpers
// ---------------------------------------------------------------------------
__device__ __forceinline__ float bf_round(float x) {
    return __bfloat162float(__float2bfloat16(x));
}
__device__ __forceinline__ float bf_add(float a_bf, float x_bf) {
    return bf_round(a_bf + x_bf);
}
// exact bf16 -> f32 widen (value identical to bf_round of the original f32)
__device__ __forceinline__ float bw_lo(uint32_t w) { return __uint_as_float(w << 16); }
__device__ __forceinline__ float bw_hi(uint32_t w) { return __uint_as_float(w & 0xFFFF0000u); }

// ---------------------------------------------------------------------------
// Kernel 0: table prep — f32 table -> bf16 (round-to-nearest-even).
// Both pool and gather read only bf16-rounded values; halves their L2 traffic.
// ---------------------------------------------------------------------------
__global__ void tprep_kernel(const float* __restrict__ table) {
    int i = blockIdx.x * blockDim.x + threadIdx.x;     // uint2 index, 65536 total
    float4 v = reinterpret_cast<const float4*>(table)[i];
    __nv_bfloat162 a = __floats2bfloat162_rn(v.x, v.y);
    __nv_bfloat162 b = __floats2bfloat162_rn(v.z, v.w);
    uint2 o;
    o.x = *reinterpret_cast<uint32_t*>(&a);
    o.y = *reinterpret_cast<uint32_t*>(&b);
    g_tb2[i] = o;
}

// ---------------------------------------------------------------------------
// Kernel 1: patch pooling, exact bf16 sequential-accumulation semantics.
// Reads bf16 table (values already rounded). Writes fp16 g_A; fused mask.
// ---------------------------------------------------------------------------
__device__ __forceinline__ int lower_bound_dev(const int* __restrict__ a, int n, int v) {
    int lo = 0, hi = n;
    while (lo < hi) {
        int mid = (lo + hi) >> 1;
        if (a[mid] < v) lo = mid + 1; else hi = mid;
    }
    return lo;
}

__global__ __launch_bounds__(256) void pool_kernel(const int* __restrict__ bytes,
                                                   const int* __restrict__ patch_ids,
                                                   float* __restrict__ mask) {
    int p = blockIdx.x;            // patch 0..511
    int b = blockIdx.y;            // batch 0..7
    const int* pid = patch_ids + b * SS;

    if (threadIdx.x == 0) {
        int mx = __ldg(&pid[SS - 1]);
        mask[b * PP + p] = (p <= mx) ? 1.0f : 0.0f;
    }

    int lo = lower_bound_dev(pid, SS, p);
    int hi = lower_bound_dev(pid, SS, p + 1);
    int cnt = hi - lo;

    int tid = threadIdx.x;         // owns dims [tid*4, tid*4+4)
    float acc0 = 0.f, acc1 = 0.f, acc2 = 0.f, acc3 = 0.f;

    for (int t = lo; t < hi; t++) {
        int byte = __ldg(&bytes[b * SS + t]);
        uint2 w = g_tb2[byte * 256 + tid];
        acc0 = bf_add(acc0, bw_lo(w.x));
        acc1 = bf_add(acc1, bw_hi(w.x));
        acc2 = bf_add(acc2, bw_lo(w.y));
        acc3 = bf_add(acc3, bw_hi(w.y));
    }

    float o0, o1, o2, o3;
    if (cnt > 0) {
        float inv = (float)cnt;
        o0 = bf_round(acc0 / inv);
        o1 = bf_round(acc1 / inv);
        o2 = bf_round(acc2 / inv);
        o3 = bf_round(acc3 / inv);
    } else {
        o0 = o1 = o2 = o3 = 0.f;
    }
    __half2 h0 = __floats2half2_rn(o0, o1);
    __half2 h1 = __floats2half2_rn(o2, o3);
    uint2 pack;
    pack.x = *reinterpret_cast<uint32_t*>(&h0);
    pack.y = *reinterpret_cast<uint32_t*>(&h1);
    size_t row = (size_t)(b * PP + p);
    reinterpret_cast<uint2*>(g_A)[row * (EE / 4) + tid] = pack;
}

// ---------------------------------------------------------------------------
// Kernel 2: W prep — transpose [K,N] f32 -> [N,K] fp16 (tiled via SMEM)
// ---------------------------------------------------------------------------
__global__ __launch_bounds__(256) void wprep_kernel(const float* __restrict__ W) {
    __shared__ float t[32][33];
    int n0 = blockIdx.x * 32, k0 = blockIdx.y * 32;
    int tx = threadIdx.x, ty = threadIdx.y;   // block (32, 8)
    #pragma unroll
    for (int i = 0; i < 32; i += 8)
        t[ty + i][tx] = W[(size_t)(k0 + ty + i) * NN + n0 + tx];
    __syncthreads();
    #pragma unroll
    for (int i = 0; i < 32; i += 8)
        g_Wt[(size_t)(n0 + ty + i) * KK + k0 + tx] = __float2half_rn(t[tx][ty + i]);
}

// ---------------------------------------------------------------------------
// Kernel 3: FUSED fp16 tensor-core GEMM + byte_embeds gather (from bf16 table).
// GEMM: CTA 128x256x64, 512 thr / 16 warps (4m x 4n), 3-stage cp.async.
// Gather per chunk: 4 LDG.64 (bf16) early, widen via SHL/AND, 4 STG.128 after
// the mma loop (~2000 cyc cover). No F2F converts.
// ---------------------------------------------------------------------------
#define BM 128
#define BN 256
#define BK 64
#define STAGES 3
#define ROWB 144                         // 128B data + 16B pad (16B-unit stride 9 mod 8 = 1)
#define A_BYTES (BM * ROWB)              // 18432
#define B_BYTES (BN * ROWB)              // 36864
#define STAGE_BYTES (A_BYTES + B_BYTES)  // 55296
#define GEMM_SMEM (STAGES * STAGE_BYTES) // 165888
#define GTHREADS 512
#define G_PER_CTA 32768                  // float4s of gather per CTA (8.4M / 256)
#define G_PER_CHUNK 2048                 // per chunk (G_PER_CTA / 16)

__device__ __forceinline__ uint32_t smem_u32(const void* p) {
    uint32_t a;
    asm("{ .reg .u64 t; cvta.to.shared.u64 t, %1; cvt.u32.u64 %0, t; }" : "=r"(a) : "l"(p));
    return a;
}
__device__ __forceinline__ void cp_async16(uint32_t saddr, const void* gaddr) {
    asm volatile("cp.async.cg.shared.global [%0], [%1], 16;\n" :: "r"(saddr), "l"(gaddr));
}
__device__ __forceinline__ void ldmatrix_x4(uint32_t* r, uint32_t addr) {
    asm volatile("ldmatrix.sync.aligned.m8n8.x4.shared.b16 {%0,%1,%2,%3}, [%4];"
                 : "=r"(r[0]), "=r"(r[1]), "=r"(r[2]), "=r"(r[3]) : "r"(addr));
}
__device__ __forceinline__ void mma_16816(float* c, const uint32_t* a, uint32_t b0, uint32_t b1) {
    asm volatile("mma.sync.aligned.m16n8k16.row.col.f32.f16.f16.f32 "
                 "{%0,%1,%2,%3}, {%4,%5,%6,%7}, {%8,%9}, {%0,%1,%2,%3};"
                 : "+f"(c[0]), "+f"(c[1]), "+f"(c[2]), "+f"(c[3])
                 : "r"(a[0]), "r"(a[1]), "r"(a[2]), "r"(a[3]), "r"(b0), "r"(b1));
}

__device__ __forceinline__ uint2 gfetch_bf16(const int* __restrict__ bytes, int u) {
    int tok = u >> 8;          // 256 float4-units per token row
    int e4 = u & 255;
    return g_tb2[__ldg(&bytes[tok]) * 256 + e4];
}
__device__ __forceinline__ void gstore_bf16(float4* out4, int u, uint2 w) {
    float4 v;
    v.x = bw_lo(w.x);
    v.y = bw_hi(w.x);
    v.z = bw_lo(w.y);
    v.w = bw_hi(w.y);
    __stcs(out4 + u, v);       // streaming: keep dead-on-arrival writes out of L2
}

__global__ __launch_bounds__(GTHREADS, 1) void gemm_mma_kernel(const float* __restrict__ bias,
                                                               float* __restrict__ C,
                                                               const int* __restrict__ bytes,
                                                               float* __restrict__ gout) {
    extern __shared__ __align__(16) char smem[];
    uint32_t sbase = smem_u32(smem);

    const int tid = threadIdx.x;
    const int lane = tid & 31;
    const int wid = tid >> 5;        // 0..15
    const int wm = wid & 3;          // 0..3 -> m offset wm*32
    const int wn = wid >> 2;         // 0..3 -> n offset wn*64
    const int bm = blockIdx.y * BM;
    const int bn = blockIdx.x * BN;
    const int cta = blockIdx.y * gridDim.x + blockIdx.x;   // 0..255

    const __half* Ag = g_A  + (size_t)bm * KK;
    const __half* Bg = g_Wt + (size_t)bn * KK;
    float4* gout4 = reinterpret_cast<float4*>(gout);

    auto load_stage = [&](int buf, int k0) {
        #pragma unroll
        for (int i = 0; i < 2; i++) {
            int unit = tid + i * GTHREADS;
            int r = unit >> 3, j = unit & 7;
            cp_async16(sbase + buf * STAGE_BYTES + r * ROWB + j * 16,
                       Ag + (size_t)r * KK + k0 + j * 8);
        }
        #pragma unroll
        for (int i = 0; i < 4; i++) {
            int unit = tid + i * GTHREADS;
            int r = unit >> 3, j = unit & 7;
            cp_async16(sbase + buf * STAGE_BYTES + A_BYTES + r * ROWB + j * 16,
                       Bg + (size_t)r * KK + k0 + j * 8);
        }
        asm volatile("cp.async.commit_group;\n");
    };

    float acc[2][8][4];
    #pragma unroll
    for (int mt = 0; mt < 2; mt++)
        #pragma unroll
        for (int nt = 0; nt < 8; nt++)
            #pragma unroll
            for (int q = 0; q < 4; q++) acc[mt][nt][q] = 0.f;

    const int NC = KK / BK;   // 16
    load_stage(0, 0);
    load_stage(1, BK);

    const int lrow = lane & 15;
    const int lcol16 = (lane >> 4) * 16;

    for (int c = 0; c < NC; c++) {
        if (c < NC - 1) {
            asm volatile("cp.async.wait_group 1;\n");
        } else {
            asm volatile("cp.async.wait_group 0;\n");
        }
        __syncthreads();   // stage c visible; readers of stage c-1 done

        if (c + 2 < NC)
            load_stage((c + 2) % STAGES, (c + 2) * BK);

        // --- gather slice: 4 bf16x4 loads issued before the mma loop ---
        const int gu = cta * G_PER_CTA + c * G_PER_CHUNK + tid;
        uint2 gv0 = gfetch_bf16(bytes, gu);
        uint2 gv1 = gfetch_bf16(bytes, gu + GTHREADS);
        uint2 gv2 = gfetch_bf16(bytes, gu + 2 * GTHREADS);
        uint2 gv3 = gfetch_bf16(bytes, gu + 3 * GTHREADS);

        uint32_t Ab = sbase + (c % STAGES) * STAGE_BYTES;
        uint32_t Bb = Ab + A_BYTES;
        uint32_t Arow = Ab + (wm * 32 + lrow) * ROWB + lcol16;
        uint32_t Brow = Bb + (wn * 64 + lrow) * ROWB + lcol16;

        #pragma unroll
        for (int ks = 0; ks < 4; ks++) {
            uint32_t af[2][4];
            #pragma unroll
            for (int mt = 0; mt < 2; mt++)
                ldmatrix_x4(af[mt], Arow + mt * 16 * ROWB + ks * 32);
            #pragma unroll
            for (int ntp = 0; ntp < 4; ntp++) {
                uint32_t bf[4];
                ldmatrix_x4(bf, Brow + ntp * 16 * ROWB + ks * 32);
                #pragma unroll
                for (int mt = 0; mt < 2; mt++) {
                    mma_16816(acc[mt][2 * ntp + 0], af[mt], bf[0], bf[2]);
                    mma_16816(acc[mt][2 * ntp + 1], af[mt], bf[1], bf[3]);
                }
            }
        }

        // stores after the full mma loop: loads have ~4 k-steps of cover
        gstore_bf16(gout4, gu, gv0);
        gstore_bf16(gout4, gu + GTHREADS, gv1);
        gstore_bf16(gout4, gu + 2 * GTHREADS, gv2);
        gstore_bf16(gout4, gu + 3 * GTHREADS, gv3);
    }

    // Epilogue: m16n8 fragment -> C. row = lane/4 (+8 for regs 2,3), col = 2*(lane%4)
    const int er = lane >> 2;
    const int ec = (lane & 3) * 2;
    #pragma unroll
    for (int mt = 0; mt < 2; mt++) {
        #pragma unroll
        for (int nt = 0; nt < 8; nt++) {
            int n = bn + wn * 64 + nt * 8 + ec;
            float b0 = bias[n], b1 = bias[n + 1];
            int m0 = bm + wm * 32 + mt * 16 + er;
            float2 o0 = make_float2(acc[mt][nt][0] + b0, acc[mt][nt][1] + b1);
            float2 o1 = make_float2(acc[mt][nt][2] + b0, acc[mt][nt][3] + b1);
            *reinterpret_cast<float2*>(C + (size_t)m0 * NN + n) = o0;
            *reinterpret_cast<float2*>(C + (size_t)(m0 + 8) * NN + n) = o1;
        }
    }
}

// ---------------------------------------------------------------------------
// Launch — wprep ∥ (tprep -> pool) -> fused GEMM+gather.
// ---------------------------------------------------------------------------
extern "C" void kernel_launch(void* const* d_in, const int* in_sizes, int n_in,
                              void* d_out, int out_size) {
    const int*   bytes    = (const int*)d_in[0];
    const int*   pids     = (const int*)d_in[1];
    const float* table    = (const float*)d_in[2];
    const float* W        = (const float*)d_in[3];
    const float* bias     = (const float*)d_in[4];

    float* out         = (float*)d_out;
    float* byte_embeds = out;                                    // 8*4096*1024
    float* patch_embs  = out + (size_t)BB * SS * EE;             // 8*512*2048
    float* mask        = patch_embs + (size_t)BB * PP * GG;      // 8*512

    static cudaStream_t s_w = nullptr;
    static cudaEvent_t e_fork = nullptr, e_w = nullptr;
    if (s_w == nullptr) {
        cudaStreamCreateWithFlags(&s_w, cudaStreamNonBlocking);
        cudaEventCreateWithFlags(&e_fork, cudaEventDisableTiming);
        cudaEventCreateWithFlags(&e_w, cudaEventDisableTiming);
        cudaFuncSetAttribute(gemm_mma_kernel,
                             cudaFuncAttributeMaxDynamicSharedMemorySize, GEMM_SMEM);
    }

    // Fork: wprep runs concurrently with tprep+pool
    cudaEventRecord(e_fork, 0);
    cudaStreamWaitEvent(s_w, e_fork, 0);
    wprep_kernel<<<dim3(NN / 32, KK / 32), dim3(32, 8), 0, s_w>>>(W);
    cudaEventRecord(e_w, s_w);

    // Main: table bf16 prep, then pool(+mask)
    tprep_kernel<<<VV * EE / 4 / 256, 256>>>(table);
    pool_kernel<<<dim3(PP, BB), 256>>>(bytes, pids, mask);

    // Main: fused GEMM + gather (after wprep + pool)
    cudaStreamWaitEvent(0, e_w, 0);
    gemm_mma_kernel<<<dim3(NN / BN, MM / BM), GTHREADS, GEMM_SMEM>>>(
        bias, patch_embs, bytes, byte_embeds);
}

// round 12
// speedup vs baseline: 4.8242x; 1.0640x over previous
#include <cuda_runtime.h>
#include <cuda_bf16.h>
#include <cuda_fp16.h>
#include <stdint.h>

// Problem constants (fixed shapes from reference)
#define BB 8
#define SS 4096
#define EE 1024
#define GG 2048
#define VV 256
#define PP 512

#define MM (BB * PP)   // 4096 GEMM M
#define NN GG          // 2048 GEMM N
#define KK EE          // 1024 GEMM K

// Scratch (device globals — no allocation allowed)
__device__ __half g_A[(size_t)MM * KK];    // pooled patch embeddings, fp16 (exact bf16 values), [M,K]
__device__ __half g_Wt[(size_t)NN * KK];   // W transposed to [N,K], fp16
__device__ uint2  g_tb2[(size_t)VV * EE / 4];  // bf16 table, 4 bf16 per uint2 (512 KB)

// ---------------------------------------------------------------------------
// bf16 emulation helpers
// ---------------------------------------------------------------------------
__device__ __forceinline__ float bf_round(float x) {
    return __bfloat162float(__float2bfloat16(x));
}
__device__ __forceinline__ float bf_add(float a_bf, float x_bf) {
    return bf_round(a_bf + x_bf);
}
// exact bf16 -> f32 widen (value identical to bf_round of the original f32)
__device__ __forceinline__ float bw_lo(uint32_t w) { return __uint_as_float(w << 16); }
__device__ __forceinline__ float bw_hi(uint32_t w) { return __uint_as_float(w & 0xFFFF0000u); }

// ---------------------------------------------------------------------------
// Kernel 0: table prep — f32 table -> bf16 (round-to-nearest-even).
// ---------------------------------------------------------------------------
__global__ void tprep_kernel(const float* __restrict__ table) {
    int i = blockIdx.x * blockDim.x + threadIdx.x;     // uint2 index, 65536 total
    float4 v = reinterpret_cast<const float4*>(table)[i];
    __nv_bfloat162 a = __floats2bfloat162_rn(v.x, v.y);
    __nv_bfloat162 b = __floats2bfloat162_rn(v.z, v.w);
    uint2 o;
    o.x = *reinterpret_cast<uint32_t*>(&a);
    o.y = *reinterpret_cast<uint32_t*>(&b);
    g_tb2[i] = o;
}

// ---------------------------------------------------------------------------
// Kernel 1: patch pooling, exact bf16 sequential-accumulation semantics.
// lo/hi searched in parallel (thread 0 / thread 32); accumulate loop batches
// 4 independent table-row loads per group, then adds in strict token order.
// ---------------------------------------------------------------------------
__device__ __forceinline__ int lower_bound_dev(const int* __restrict__ a, int n, int v) {
    int lo = 0, hi = n;
    while (lo < hi) {
        int mid = (lo + hi) >> 1;
        if (a[mid] < v) lo = mid + 1; else hi = mid;
    }
    return lo;
}

__global__ __launch_bounds__(256) void pool_kernel(const int* __restrict__ bytes,
                                                   const int* __restrict__ patch_ids,
                                                   float* __restrict__ mask) {
    __shared__ int s_lo, s_hi;
    int p = blockIdx.x;            // patch 0..511
    int b = blockIdx.y;            // batch 0..7
    const int* pid = patch_ids + b * SS;

    if (threadIdx.x == 0) {
        s_lo = lower_bound_dev(pid, SS, p);
        int mx = __ldg(&pid[SS - 1]);
        mask[b * PP + p] = (p <= mx) ? 1.0f : 0.0f;
    } else if (threadIdx.x == 32) {
        s_hi = lower_bound_dev(pid, SS, p + 1);
    }
    __syncthreads();
    const int lo = s_lo;
    const int hi = s_hi;
    const int cnt = hi - lo;

    const int tid = threadIdx.x;   // owns dims [tid*4, tid*4+4)
    const int* bp = bytes + b * SS;
    float a0 = 0.f, a1 = 0.f, a2 = 0.f, a3 = 0.f;

    for (int t0 = lo; t0 < hi; t0 += 4) {
        int rem = hi - t0;
        // batch the independent loads (latency overlaps), then add in order
        uint2 w0, w1, w2, w3;
        w0 = g_tb2[__ldg(bp + t0) * 256 + tid];
        if (rem > 1) w1 = g_tb2[__ldg(bp + t0 + 1) * 256 + tid];
        if (rem > 2) w2 = g_tb2[__ldg(bp + t0 + 2) * 256 + tid];
        if (rem > 3) w3 = g_tb2[__ldg(bp + t0 + 3) * 256 + tid];

        a0 = bf_add(a0, bw_lo(w0.x)); a1 = bf_add(a1, bw_hi(w0.x));
        a2 = bf_add(a2, bw_lo(w0.y)); a3 = bf_add(a3, bw_hi(w0.y));
        if (rem > 1) {
            a0 = bf_add(a0, bw_lo(w1.x)); a1 = bf_add(a1, bw_hi(w1.x));
            a2 = bf_add(a2, bw_lo(w1.y)); a3 = bf_add(a3, bw_hi(w1.y));
        }
        if (rem > 2) {
            a0 = bf_add(a0, bw_lo(w2.x)); a1 = bf_add(a1, bw_hi(w2.x));
            a2 = bf_add(a2, bw_lo(w2.y)); a3 = bf_add(a3, bw_hi(w2.y));
        }
        if (rem > 3) {
            a0 = bf_add(a0, bw_lo(w3.x)); a1 = bf_add(a1, bw_hi(w3.x));
            a2 = bf_add(a2, bw_lo(w3.y)); a3 = bf_add(a3, bw_hi(w3.y));
        }
    }

    float o0, o1, o2, o3;
    if (cnt > 0) {
        float inv = (float)cnt;
        o0 = bf_round(a0 / inv);
        o1 = bf_round(a1 / inv);
        o2 = bf_round(a2 / inv);
        o3 = bf_round(a3 / inv);
    } else {
        o0 = o1 = o2 = o3 = 0.f;
    }
    __half2 h0 = __floats2half2_rn(o0, o1);
    __half2 h1 = __floats2half2_rn(o2, o3);
    uint2 pack;
    pack.x = *reinterpret_cast<uint32_t*>(&h0);
    pack.y = *reinterpret_cast<uint32_t*>(&h1);
    size_t row = (size_t)(b * PP + p);
    reinterpret_cast<uint2*>(g_A)[row * (EE / 4) + tid] = pack;
}

// ---------------------------------------------------------------------------
// Kernel 2: W prep — transpose [K,N] f32 -> [N,K] fp16 (tiled via SMEM)
// ---------------------------------------------------------------------------
__global__ __launch_bounds__(256) void wprep_kernel(const float* __restrict__ W) {
    __shared__ float t[32][33];
    int n0 = blockIdx.x * 32, k0 = blockIdx.y * 32;
    int tx = threadIdx.x, ty = threadIdx.y;   // block (32, 8)
    #pragma unroll
    for (int i = 0; i < 32; i += 8)
        t[ty + i][tx] = W[(size_t)(k0 + ty + i) * NN + n0 + tx];
    __syncthreads();
    #pragma unroll
    for (int i = 0; i < 32; i += 8)
        g_Wt[(size_t)(n0 + ty + i) * KK + k0 + tx] = __float2half_rn(t[tx][ty + i]);
}

// ---------------------------------------------------------------------------
// Kernel 3: FUSED fp16 tensor-core GEMM + byte_embeds gather (from bf16 table).
// GEMM: CTA 128x256x64, 512 thr / 16 warps (4m x 4n), 3-stage cp.async.
// ---------------------------------------------------------------------------
#define BM 128
#define BN 256
#define BK 64
#define STAGES 3
#define ROWB 144                         // 128B data + 16B pad (16B-unit stride 9 mod 8 = 1)
#define A_BYTES (BM * ROWB)              // 18432
#define B_BYTES (BN * ROWB)              // 36864
#define STAGE_BYTES (A_BYTES + B_BYTES)  // 55296
#define GEMM_SMEM (STAGES * STAGE_BYTES) // 165888
#define GTHREADS 512
#define G_PER_CTA 32768                  // float4s of gather per CTA (8.4M / 256)
#define G_PER_CHUNK 2048                 // per chunk (G_PER_CTA / 16)

__device__ __forceinline__ uint32_t smem_u32(const void* p) {
    uint32_t a;
    asm("{ .reg .u64 t; cvta.to.shared.u64 t, %1; cvt.u32.u64 %0, t; }" : "=r"(a) : "l"(p));
    return a;
}
__device__ __forceinline__ void cp_async16(uint32_t saddr, const void* gaddr) {
    asm volatile("cp.async.cg.shared.global [%0], [%1], 16;\n" :: "r"(saddr), "l"(gaddr));
}
__device__ __forceinline__ void ldmatrix_x4(uint32_t* r, uint32_t addr) {
    asm volatile("ldmatrix.sync.aligned.m8n8.x4.shared.b16 {%0,%1,%2,%3}, [%4];"
                 : "=r"(r[0]), "=r"(r[1]), "=r"(r[2]), "=r"(r[3]) : "r"(addr));
}
__device__ __forceinline__ void mma_16816(float* c, const uint32_t* a, uint32_t b0, uint32_t b1) {
    asm volatile("mma.sync.aligned.m16n8k16.row.col.f32.f16.f16.f32 "
                 "{%0,%1,%2,%3}, {%4,%5,%6,%7}, {%8,%9}, {%0,%1,%2,%3};"
                 : "+f"(c[0]), "+f"(c[1]), "+f"(c[2]), "+f"(c[3])
                 : "r"(a[0]), "r"(a[1]), "r"(a[2]), "r"(a[3]), "r"(b0), "r"(b1));
}

__device__ __forceinline__ uint2 gfetch_bf16(const int* __restrict__ bytes, int u) {
    int tok = u >> 8;          // 256 float4-units per token row
    int e4 = u & 255;
    return g_tb2[__ldg(&bytes[tok]) * 256 + e4];
}
__device__ __forceinline__ void gstore_bf16(float4* out4, int u, uint2 w) {
    float4 v;
    v.x = bw_lo(w.x);
    v.y = bw_hi(w.x);
    v.z = bw_lo(w.y);
    v.w = bw_hi(w.y);
    __stcs(out4 + u, v);       // streaming: keep dead-on-arrival writes out of L2
}

__global__ __launch_bounds__(GTHREADS, 1) void gemm_mma_kernel(const float* __restrict__ bias,
                                                               float* __restrict__ C,
                                                               const int* __restrict__ bytes,
                                                               float* __restrict__ gout) {
    extern __shared__ __align__(16) char smem[];
    uint32_t sbase = smem_u32(smem);

    const int tid = threadIdx.x;
    const int lane = tid & 31;
    const int wid = tid >> 5;        // 0..15
    const int wm = wid & 3;          // 0..3 -> m offset wm*32
    const int wn = wid >> 2;         // 0..3 -> n offset wn*64
    const int bm = blockIdx.y * BM;
    const int bn = blockIdx.x * BN;
    const int cta = blockIdx.y * gridDim.x + blockIdx.x;   // 0..255

    const __half* Ag = g_A  + (size_t)bm * KK;
    const __half* Bg = g_Wt + (size_t)bn * KK;
    float4* gout4 = reinterpret_cast<float4*>(gout);

    auto load_stage = [&](int buf, int k0) {
        #pragma unroll
        for (int i = 0; i < 2; i++) {
            int unit = tid + i * GTHREADS;
            int r = unit >> 3, j = unit & 7;
            cp_async16(sbase + buf * STAGE_BYTES + r * ROWB + j * 16,
                       Ag + (size_t)r * KK + k0 + j * 8);
        }
        #pragma unroll
        for (int i = 0; i < 4; i++) {
            int unit = tid + i * GTHREADS;
            int r = unit >> 3, j = unit & 7;
            cp_async16(sbase + buf * STAGE_BYTES + A_BYTES + r * ROWB + j * 16,
                       Bg + (size_t)r * KK + k0 + j * 8);
        }
        asm volatile("cp.async.commit_group;\n");
    };

    float acc[2][8][4];
    #pragma unroll
    for (int mt = 0; mt < 2; mt++)
        #pragma unroll
        for (int nt = 0; nt < 8; nt++)
            #pragma unroll
            for (int q = 0; q < 4; q++) acc[mt][nt][q] = 0.f;

    const int NC = KK / BK;   // 16
    load_stage(0, 0);
    load_stage(1, BK);

    const int lrow = lane & 15;
    const int lcol16 = (lane >> 4) * 16;

    for (int c = 0; c < NC; c++) {
        if (c < NC - 1) {
            asm volatile("cp.async.wait_group 1;\n");
        } else {
            asm volatile("cp.async.wait_group 0;\n");
        }
        __syncthreads();   // stage c visible; readers of stage c-1 done

        if (c + 2 < NC)
            load_stage((c + 2) % STAGES, (c + 2) * BK);

        // --- gather slice: 4 bf16x4 loads issued before the mma loop ---
        const int gu = cta * G_PER_CTA + c * G_PER_CHUNK + tid;
        uint2 gv0 = gfetch_bf16(bytes, gu);
        uint2 gv1 = gfetch_bf16(bytes, gu + GTHREADS);
        uint2 gv2 = gfetch_bf16(bytes, gu + 2 * GTHREADS);
        uint2 gv3 = gfetch_bf16(bytes, gu + 3 * GTHREADS);

        uint32_t Ab = sbase + (c % STAGES) * STAGE_BYTES;
        uint32_t Bb = Ab + A_BYTES;
        uint32_t Arow = Ab + (wm * 32 + lrow) * ROWB + lcol16;
        uint32_t Brow = Bb + (wn * 64 + lrow) * ROWB + lcol16;

        #pragma unroll
        for (int ks = 0; ks < 4; ks++) {
            uint32_t af[2][4];
            #pragma unroll
            for (int mt = 0; mt < 2; mt++)
                ldmatrix_x4(af[mt], Arow + mt * 16 * ROWB + ks * 32);
            #pragma unroll
            for (int ntp = 0; ntp < 4; ntp++) {
                uint32_t bf[4];
                ldmatrix_x4(bf, Brow + ntp * 16 * ROWB + ks * 32);
                #pragma unroll
                for (int mt = 0; mt < 2; mt++) {
                    mma_16816(acc[mt][2 * ntp + 0], af[mt], bf[0], bf[2]);
                    mma_16816(acc[mt][2 * ntp + 1], af[mt], bf[1], bf[3]);
                }
            }
        }

        // stores after the full mma loop: loads have ~4 k-steps of cover
        gstore_bf16(gout4, gu, gv0);
        gstore_bf16(gout4, gu + GTHREADS, gv1);
        gstore_bf16(gout4, gu + 2 * GTHREADS, gv2);
        gstore_bf16(gout4, gu + 3 * GTHREADS, gv3);
    }

    // Epilogue: m16n8 fragment -> C. row = lane/4 (+8 for regs 2,3), col = 2*(lane%4)
    const int er = lane >> 2;
    const int ec = (lane & 3) * 2;
    #pragma unroll
    for (int mt = 0; mt < 2; mt++) {
        #pragma unroll
        for (int nt = 0; nt < 8; nt++) {
            int n = bn + wn * 64 + nt * 8 + ec;
            float b0 = bias[n], b1 = bias[n + 1];
            int m0 = bm + wm * 32 + mt * 16 + er;
            float2 o0 = make_float2(acc[mt][nt][0] + b0, acc[mt][nt][1] + b1);
            float2 o1 = make_float2(acc[mt][nt][2] + b0, acc[mt][nt][3] + b1);
            *reinterpret_cast<float2*>(C + (size_t)m0 * NN + n) = o0;
            *reinterpret_cast<float2*>(C + (size_t)(m0 + 8) * NN + n) = o1;
        }
    }
}

// ---------------------------------------------------------------------------
// Launch — wprep ∥ (tprep -> pool) -> fused GEMM+gather.
// ---------------------------------------------------------------------------
extern "C" void kernel_launch(void* const* d_in, const int* in_sizes, int n_in,
                              void* d_out, int out_size) {
    const int*   bytes    = (const int*)d_in[0];
    const int*   pids     = (const int*)d_in[1];
    const float* table    = (const float*)d_in[2];
    const float* W        = (const float*)d_in[3];
    const float* bias     = (const float*)d_in[4];

    float* out         = (float*)d_out;
    float* byte_embeds = out;                                    // 8*4096*1024
    float* patch_embs  = out + (size_t)BB * SS * EE;             // 8*512*2048
    float* mask        = patch_embs + (size_t)BB * PP * GG;      // 8*512

    static cudaStream_t s_w = nullptr;
    static cudaEvent_t e_fork = nullptr, e_w = nullptr;
    if (s_w == nullptr) {
        cudaStreamCreateWithFlags(&s_w, cudaStreamNonBlocking);
        cudaEventCreateWithFlags(&e_fork, cudaEventDisableTiming);
        cudaEventCreateWithFlags(&e_w, cudaEventDisableTiming);
        cudaFuncSetAttribute(gemm_mma_kernel,
                             cudaFuncAttributeMaxDynamicSharedMemorySize, GEMM_SMEM);
    }

    // Fork: wprep runs concurrently with tprep+pool
    cudaEventRecord(e_fork, 0);
    cudaStreamWaitEvent(s_w, e_fork, 0);
    wprep_kernel<<<dim3(NN / 32, KK / 32), dim3(32, 8), 0, s_w>>>(W);
    cudaEventRecord(e_w, s_w);

    // Main: table bf16 prep, then pool(+mask)
    tprep_kernel<<<VV * EE / 4 / 256, 256>>>(table);
    pool_kernel<<<dim3(PP, BB), 256>>>(bytes, pids, mask);

    // Main: fused GEMM + gather (after wprep + pool)
    cudaStreamWaitEvent(0, e_w, 0);
    gemm_mma_kernel<<<dim3(NN / BN, MM / BM), GTHREADS, GEMM_SMEM>>>(
        bias, patch_embs, bytes, byte_embeds);
}